// round 3
// baseline (speedup 1.0000x reference)
#include <cuda_runtime.h>

#define BN 65536
#define CN 128
#define DN 32
#define KN 10
#define DE 33            // extended dim (z, 1)
#define PSTRIDE 612      // padded packed upper-triangle size of 33x33 (rows padded to 4 floats)
#define EPSV 1e-12f

typedef unsigned long long ull;

// Packed per-cluster quadratic forms (see pre_kernel). 128*612*4B = 313 KB, L2-resident.
__device__ float g_P[CN * PSTRIDE];

__host__ __device__ __forceinline__ int padlen_f(int d) { return ((36 - d) >> 2) << 2; }

// ---- f32x2 packed-math helpers (Blackwell dual-lane fp32; PTX-only) ----
__device__ __forceinline__ ull fma2(ull a, ull b, ull c) {
    ull d; asm("fma.rn.f32x2 %0, %1, %2, %3;" : "=l"(d) : "l"(a), "l"(b), "l"(c)); return d;
}
__device__ __forceinline__ ull add2(ull a, ull b) {
    ull d; asm("add.rn.f32x2 %0, %1, %2;" : "=l"(d) : "l"(a), "l"(b)); return d;
}
__device__ __forceinline__ ull pack2(float lo, float hi) {
    ull r; asm("mov.b64 %0, {%1, %2};" : "=l"(r) : "f"(lo), "f"(hi)); return r;
}
__device__ __forceinline__ void unpack2(ull v, float& lo, float& hi) {
    asm("mov.b64 {%0, %1}, %2;" : "=f"(lo), "=f"(hi) : "l"(v));
}
__device__ __forceinline__ void lds_v2b64(ull& a, ull& b, unsigned addr) {
    asm("ld.shared.v2.b64 {%0, %1}, [%2];" : "=l"(a), "=l"(b) : "r"(addr));
}

// ---------------------------------------------------------------------------
// Pre-kernel: build M_c = [[W, -W mu],[-mu'W, mu'W mu]] packed upper triangle,
// diagonal pre-scaled by 0.5, rows zero-padded to float4 boundaries.
// ---------------------------------------------------------------------------
__global__ void pre_kernel(const float* __restrict__ mu,
                           const float* __restrict__ S_inv) {
    int c = blockIdx.x;
    int t = threadIdx.x;
    __shared__ float sSm[DN];
    __shared__ float sT3;
    const float* W = S_inv + (size_t)c * DN * DN;
    const float* m = mu + (size_t)c * DN;

    if (t < DN) {
        float acc = 0.f;
        #pragma unroll
        for (int e = 0; e < DN; ++e) acc = fmaf(W[t * DN + e], m[e], acc);
        sSm[t] = acc;
    }
    __syncthreads();
    if (t == 0) {
        float acc = 0.f;
        #pragma unroll
        for (int d = 0; d < DN; ++d) acc = fmaf(m[d], sSm[d], acc);
        sT3 = acc;
    }
    __syncthreads();

    if (t < DE) {
        int d = t;
        int rowstart = 0;
        for (int i = 0; i < d; ++i) rowstart += padlen_f(i);
        int pl = padlen_f(d);
        float* dst = g_P + (size_t)c * PSTRIDE + rowstart;
        for (int j = 0; j < pl; ++j) {
            int e = d + j;
            float v = 0.f;
            if (e < DE) {
                if (e < DN)        v = W[d * DN + e];
                else if (d < DN)   v = -sSm[d];
                else               v = sT3;
                if (e == d)        v *= 0.5f;
            }
            dst[j] = v;
        }
    }
}

// ---------------------------------------------------------------------------
// Main kernel: one thread = one sample; packed f32x2 row dot-products.
// ---------------------------------------------------------------------------
__global__ __launch_bounds__(256, 2)
void egauss_main(const float* __restrict__ data,
                 const int* __restrict__ labels,
                 float* __restrict__ out,
                 int out_size) {
    __shared__ float sP[2][PSTRIDE];
    __shared__ int scls[CN];

    int tid = threadIdx.x;

    if (tid < CN) {
        const int* row = labels + tid * KN;
        int kc = 0;
        #pragma unroll
        for (int k = 0; k < KN; ++k) if (row[k] != 0) kc = k;
        scls[tid] = kc;
    }

    long b = (long)blockIdx.x + (long)gridDim.x * tid;
    bool active = b < BN;

    // Load z and build dual packings: zA[k]=(z2k, z2k+1), zB[k]=(z2k+1, z2k+2).
    float zf[32];
    #pragma unroll
    for (int i = 0; i < 8; ++i) {
        float4 v = make_float4(0.f, 0.f, 0.f, 0.f);
        if (active) v = ((const float4*)(data + b * DN))[i];
        zf[4 * i + 0] = v.x; zf[4 * i + 1] = v.y;
        zf[4 * i + 2] = v.z; zf[4 * i + 3] = v.w;
    }
    ull zA[18], zB[17];
    #pragma unroll
    for (int k = 0; k < 16; ++k) zA[k] = pack2(zf[2 * k], zf[2 * k + 1]);
    zA[16] = pack2(1.f, 0.f);   // (z32=1, z33=0)
    zA[17] = 0ull;              // (z34, z35) = (0,0)
    #pragma unroll
    for (int k = 0; k < 15; ++k) zB[k] = pack2(zf[2 * k + 1], zf[2 * k + 2]);
    zB[15] = pack2(zf[31], 1.f);  // (z31, z32=1)
    zB[16] = 0ull;                // (z33, z34)

    unsigned sPaddr = (unsigned)__cvta_generic_to_shared(&sP[0][0]);

    // stage cluster 0
    bool have = tid < (PSTRIDE / 4);   // 153 float4 per cluster
    if (have) {
        float4 v = ((const float4*)g_P)[tid];
        ((float4*)sP[0])[tid] = v;
    }
    __syncthreads();

    float scores[KN];
    #pragma unroll
    for (int k = 0; k < KN; ++k) scores[k] = 0.f;
    float gsum = 0.f, gbest = -1.f;
    int cbest = 0;

    for (int c = 0; c < CN; ++c) {
        int cur = c & 1;

        // prefetch next cluster's coefficients (L2 hit, hidden under FMA block)
        float4 st = make_float4(0.f, 0.f, 0.f, 0.f);
        bool pf = have && (c + 1 < CN);
        if (pf) st = ((const float4*)(g_P + (size_t)(c + 1) * PSTRIDE))[tid];

        unsigned base = sPaddr + (unsigned)(cur * PSTRIDE * 4);

        // halfq = z' M z / 2 via packed upper triangle, f32x2 lanes
        ull halfq2 = 0ull;
        float zc0 = 0.f, zc1 = 0.f;
        {
            int off = 0;
            #pragma unroll
            for (int d = 0; d < DE; ++d) {
                const int pl = ((36 - d) >> 2) << 2;   // compile-time per unrolled d
                const int nq = pl >> 2;
                const int kz = d >> 1;
                ull acc0 = 0ull, acc1 = 0ull;
                #pragma unroll
                for (int q = 0; q < nq; ++q) {
                    ull c0, c1;
                    lds_v2b64(c0, c1, base + (unsigned)((off + 4 * q) * 4));
                    ull zp0 = (d & 1) ? zB[kz + 2 * q]     : zA[kz + 2 * q];
                    ull zp1 = (d & 1) ? zB[kz + 2 * q + 1] : zA[kz + 2 * q + 1];
                    acc0 = fma2(c0, zp0, acc0);
                    acc1 = fma2(c1, zp1, acc1);
                }
                acc0 = add2(acc0, acc1);
                if ((d & 1) == 0) unpack2(zA[kz], zc0, zc1);  // (z_d, z_{d+1})
                float zd = (d & 1) ? zc1 : zc0;
                halfq2 = fma2(pack2(zd, zd), acc0, halfq2);
                off += pl;
            }
        }
        float hl, hh;
        unpack2(halfq2, hl, hh);
        float g = expf(-(hl + hh));

        gsum += g;
        if (g > gbest) { gbest = g; cbest = c; }   // strict > == first-max (jnp)
        int kc = scls[c];
        #pragma unroll
        for (int k = 0; k < KN; ++k)
            if (kc == k) scores[k] += g;

        if (pf) ((float4*)sP[cur ^ 1])[tid] = st;
        __syncthreads();
    }

    if (active) {
        float inv = 1.f / (gsum + EPSV);
        float sbest = -1.f;
        int pbest = 0;
        float* os = out + b * KN;
        #pragma unroll
        for (int k = 0; k < KN; ++k) {
            float s = scores[k] * inv;
            os[k] = s;
            if (s > sbest) { sbest = s; pbest = k; }
        }
        long bb = (long)BN * KN;
        if (out_size >= bb + BN)       out[bb + b] = (float)pbest;
        if (out_size >= bb + 2 * BN)   out[bb + BN + b] = (float)cbest;
    }
}

extern "C" void kernel_launch(void* const* d_in, const int* in_sizes, int n_in,
                              void* d_out, int out_size) {
    const float* data   = (const float*)d_in[0];
    const float* mu     = (const float*)d_in[1];
    const float* S_inv  = (const float*)d_in[2];
    const int*   labels = (const int*)d_in[3];

    pre_kernel<<<CN, 64>>>(mu, S_inv);
    egauss_main<<<296, 256>>>(data, labels, (float*)d_out, out_size);
}

// round 4
// speedup vs baseline: 1.4421x; 1.4421x over previous
#include <cuda_runtime.h>

#define BN 65536
#define CN 128
#define DN 32
#define KN 10
#define DE 33            // extended dim (z, 1)
#define PSTRIDE 612      // padded packed upper-triangle size of 33x33 (rows padded to 4 floats)
#define EPSV 1e-12f
#define STRIDE 32768     // 128 blocks * 256 threads

// Packed per-cluster quadratic forms (see pre_kernel). 128*612*4B = 313 KB, L2-resident.
__device__ float g_P[CN * PSTRIDE];

__host__ __device__ __forceinline__ int padlen_f(int d) { return ((36 - d) >> 2) << 2; }

// ---------------------------------------------------------------------------
// Pre-kernel: build M_c = [[W, -W mu],[-mu'W, mu'W mu]] packed upper triangle,
// diagonal pre-scaled by 0.5, rows zero-padded to float4 boundaries.
// ---------------------------------------------------------------------------
__global__ void pre_kernel(const float* __restrict__ mu,
                           const float* __restrict__ S_inv) {
    int c = blockIdx.x;
    int t = threadIdx.x;
    __shared__ float sSm[DN];
    __shared__ float sT3;
    const float* W = S_inv + (size_t)c * DN * DN;
    const float* m = mu + (size_t)c * DN;

    if (t < DN) {
        float acc = 0.f;
        #pragma unroll
        for (int e = 0; e < DN; ++e) acc = fmaf(W[t * DN + e], m[e], acc);
        sSm[t] = acc;
    }
    __syncthreads();
    if (t == 0) {
        float acc = 0.f;
        #pragma unroll
        for (int d = 0; d < DN; ++d) acc = fmaf(m[d], sSm[d], acc);
        sT3 = acc;
    }
    __syncthreads();

    if (t < DE) {
        int d = t;
        int rowstart = 0;
        for (int i = 0; i < d; ++i) rowstart += padlen_f(i);
        int pl = padlen_f(d);
        float* dst = g_P + (size_t)c * PSTRIDE + rowstart;
        for (int j = 0; j < pl; ++j) {
            int e = d + j;
            float v = 0.f;
            if (e < DE) {
                if (e < DN)        v = W[d * DN + e];
                else if (d < DN)   v = -sSm[d];
                else               v = sT3;
                if (e == d)        v *= 0.5f;
            }
            dst[j] = v;
        }
    }
}

// ---------------------------------------------------------------------------
// Main kernel: one thread = TWO samples (b and b+STRIDE). Each cluster's
// packed coefficients are loaded from shared once and feed both samples'
// dot products (LDS per sample halved vs 1-sample version).
// grid = 128, block = 256: exactly 65536 samples, 1 CTA per SM.
// ---------------------------------------------------------------------------
__global__ __launch_bounds__(256, 1)
void egauss_main(const float* __restrict__ data,
                 const int* __restrict__ labels,
                 float* __restrict__ out,
                 int out_size) {
    __shared__ float sP[2][PSTRIDE];
    __shared__ int scls[CN];

    int tid = threadIdx.x;

    if (tid < CN) {
        const int* row = labels + tid * KN;
        int kc = 0;
        #pragma unroll
        for (int k = 0; k < KN; ++k) if (row[k] != 0) kc = k;
        scls[tid] = kc;
    }

    int b0 = blockIdx.x * 256 + tid;      // < 32768
    int b1 = b0 + STRIDE;                  // < 65536

    float z0[36], z1[36];
    #pragma unroll
    for (int i = 0; i < 8; ++i) {
        float4 v0 = ((const float4*)(data + (size_t)b0 * DN))[i];
        float4 v1 = ((const float4*)(data + (size_t)b1 * DN))[i];
        z0[4 * i + 0] = v0.x; z0[4 * i + 1] = v0.y;
        z0[4 * i + 2] = v0.z; z0[4 * i + 3] = v0.w;
        z1[4 * i + 0] = v1.x; z1[4 * i + 1] = v1.y;
        z1[4 * i + 2] = v1.z; z1[4 * i + 3] = v1.w;
    }
    z0[32] = 1.f; z0[33] = 0.f; z0[34] = 0.f; z0[35] = 0.f;
    z1[32] = 1.f; z1[33] = 0.f; z1[34] = 0.f; z1[35] = 0.f;

    // stage cluster 0
    bool have = tid < (PSTRIDE / 4);   // 153 float4 per cluster
    if (have) {
        float4 v = ((const float4*)g_P)[tid];
        ((float4*)sP[0])[tid] = v;
    }
    __syncthreads();

    float sc0[KN], sc1[KN];
    #pragma unroll
    for (int k = 0; k < KN; ++k) { sc0[k] = 0.f; sc1[k] = 0.f; }
    float gsum0 = 0.f, gbest0 = -1.f;
    float gsum1 = 0.f, gbest1 = -1.f;
    int cbest0 = 0, cbest1 = 0;

    for (int c = 0; c < CN; ++c) {
        int cur = c & 1;

        // prefetch next cluster's coefficients (L2 hit, hidden under FMA block)
        float4 st = make_float4(0.f, 0.f, 0.f, 0.f);
        bool pf = have && (c + 1 < CN);
        if (pf) st = ((const float4*)(g_P + (size_t)(c + 1) * PSTRIDE))[tid];

        float hq0 = 0.f, hq1 = 0.f;
        {
            const float* p = sP[cur];
            int off = 0;
            #pragma unroll
            for (int d = 0; d < DE; ++d) {
                const int pl = ((36 - d) >> 2) << 2;   // compile-time per unrolled d
                float a0 = 0.f, a1 = 0.f;
                #pragma unroll
                for (int j = 0; j < pl; ++j) {
                    float cf = p[off + j];
                    a0 = fmaf(cf, z0[d + j], a0);
                    a1 = fmaf(cf, z1[d + j], a1);
                }
                hq0 = fmaf(z0[d], a0, hq0);
                hq1 = fmaf(z1[d], a1, hq1);
                off += pl;
            }
        }

        float g0 = __expf(-hq0);
        float g1 = __expf(-hq1);
        gsum0 += g0; gsum1 += g1;
        if (g0 > gbest0) { gbest0 = g0; cbest0 = c; }   // strict > == first-max (jnp)
        if (g1 > gbest1) { gbest1 = g1; cbest1 = c; }
        int kc = scls[c];
        #pragma unroll
        for (int k = 0; k < KN; ++k) {
            if (kc == k) { sc0[k] += g0; sc1[k] += g1; }
        }

        if (pf) ((float4*)sP[cur ^ 1])[tid] = st;
        __syncthreads();
    }

    // epilogue for both samples
    {
        float inv = 1.f / (gsum0 + EPSV);
        float sbest = -1.f; int pbest = 0;
        float* os = out + (size_t)b0 * KN;
        #pragma unroll
        for (int k = 0; k < KN; ++k) {
            float s = sc0[k] * inv;
            os[k] = s;
            if (s > sbest) { sbest = s; pbest = k; }
        }
        long bb = (long)BN * KN;
        if (out_size >= bb + BN)       out[bb + b0] = (float)pbest;
        if (out_size >= bb + 2 * BN)   out[bb + BN + b0] = (float)cbest0;
    }
    {
        float inv = 1.f / (gsum1 + EPSV);
        float sbest = -1.f; int pbest = 0;
        float* os = out + (size_t)b1 * KN;
        #pragma unroll
        for (int k = 0; k < KN; ++k) {
            float s = sc1[k] * inv;
            os[k] = s;
            if (s > sbest) { sbest = s; pbest = k; }
        }
        long bb = (long)BN * KN;
        if (out_size >= bb + BN)       out[bb + b1] = (float)pbest;
        if (out_size >= bb + 2 * BN)   out[bb + BN + b1] = (float)cbest1;
    }
}

extern "C" void kernel_launch(void* const* d_in, const int* in_sizes, int n_in,
                              void* d_out, int out_size) {
    const float* data   = (const float*)d_in[0];
    const float* mu     = (const float*)d_in[1];
    const float* S_inv  = (const float*)d_in[2];
    const int*   labels = (const int*)d_in[3];

    pre_kernel<<<CN, 64>>>(mu, S_inv);
    egauss_main<<<128, 256>>>(data, labels, (float*)d_out, out_size);
}

// round 6
// speedup vs baseline: 1.7556x; 1.2174x over previous
#include <cuda_runtime.h>
#include <cstdint>

#define BN 65536
#define CN 128
#define DN 32
#define KN 10
#define EPSV 1e-12f
#define HB 32768            // samples per lane-half
#define NSLOT 578           // padded packed coeff slots (rows padded to even)
#define CLBYTES (NSLOT * 8) // 4624 B per cluster (duplicated-pair image)

typedef unsigned long long ull;

// Duplicated-pair coefficient image: per cluster, NSLOT float2(c,c). 592 KB, L2-resident.
__device__ unsigned char g_P2[CN * CLBYTES];
// Per-half partials: [half][field][sample]; fields 0..9 scores, 10 gsum, 11 gbest, 12 cbest
__device__ float g_part[2][13][BN];

// row start (in 8B slots) and slot count, rows padded to even length
__host__ __device__ __forceinline__ constexpr int rs2(int i) {
    return 33 * i - (i * (i - 1)) / 2 + ((i + 1) >> 1);
}

// ---- f32x2 helpers (dual-lane fp32; plain-sm_103-legal PTX, proven in R3) ----
__device__ __forceinline__ ull fma2(ull a, ull b, ull c) {
    ull d; asm("fma.rn.f32x2 %0, %1, %2, %3;" : "=l"(d) : "l"(a), "l"(b), "l"(c)); return d;
}
__device__ __forceinline__ ull add2(ull a, ull b) {
    ull d; asm("add.rn.f32x2 %0, %1, %2;" : "=l"(d) : "l"(a), "l"(b)); return d;
}
__device__ __forceinline__ ull pack2(float lo, float hi) {
    ull r; asm("mov.b64 %0, {%1, %2};" : "=l"(r) : "f"(lo), "f"(hi)); return r;
}
__device__ __forceinline__ void unpack2(ull v, float& lo, float& hi) {
    asm("mov.b64 {%0, %1}, %2;" : "=f"(lo), "=f"(hi) : "l"(v));
}
__device__ __forceinline__ void lds_v2b64(ull& a, ull& b, unsigned addr) {
    asm("ld.shared.v2.b64 {%0, %1}, [%2];" : "=l"(a), "=l"(b) : "r"(addr));
}

// ---------------------------------------------------------------------------
// Pre-kernel: C(i,j) = 0.5 * Mext[i][j] * (i==j ? 1 : 2), duplicated into
// float2(c,c) at padded slot rs2(i)+(j-i). Padding slots stay zero (.bss).
// ---------------------------------------------------------------------------
__global__ void pre_kernel(const float* __restrict__ mu,
                           const float* __restrict__ S_inv) {
    int c = blockIdx.x, t = threadIdx.x;
    __shared__ float sSm[DN];
    __shared__ float sT3;
    const float* W = S_inv + (size_t)c * DN * DN;
    const float* m = mu + (size_t)c * DN;

    if (t < DN) {
        float a = 0.f;
        #pragma unroll
        for (int e = 0; e < DN; ++e) a = fmaf(W[t * DN + e], m[e], a);
        sSm[t] = a;
    }
    __syncthreads();
    if (t == 0) {
        float a = 0.f;
        #pragma unroll
        for (int d = 0; d < DN; ++d) a = fmaf(m[d], sSm[d], a);
        sT3 = a;
    }
    __syncthreads();

    for (int k = t; k < 561; k += blockDim.x) {
        // triangle index -> (i, j)
        int i = 0;
        while (i < 32 && k >= 33 * (i + 1) - ((i + 1) * i) / 2) ++i;
        int j = i + (k - (33 * i - (i * (i - 1)) / 2));
        float Mv;
        if (i < 32 && j < 32)      Mv = W[i * DN + j];
        else if (i < 32)           Mv = -sSm[i];
        else                       Mv = sT3;
        float Cv = 0.5f * Mv * ((i == j) ? 1.f : 2.f);

        int slot = rs2(i) + (j - i);
        float2* dst = (float2*)(g_P2 + (size_t)c * CLBYTES);
        dst[slot] = make_float2(Cv, Cv);
    }
}

// ---------------------------------------------------------------------------
// Main kernel: 1024 CTAs x 64 threads. Thread = sample-pair (b0=p, b1=p+32768)
// living in the two f32x2 lanes. CTA handles 64 clusters (half split).
// ---------------------------------------------------------------------------
__global__ __launch_bounds__(64, 7)
void egauss2(const float* __restrict__ data,
             const int* __restrict__ labels) {
    __shared__ uint4 sbuf[2][NSLOT / 2];   // 2 x 4624 B
    __shared__ int scls[64];

    int tid = threadIdx.x;
    int half = blockIdx.x >> 9;            // 0..511 -> half 0, 512..1023 -> half 1
    int blk = blockIdx.x & 511;
    int cbase = half * 64;

    // cluster -> label index for this half's 64 clusters
    {
        const int* row = labels + (cbase + tid) * KN;
        int kc = 0;
        #pragma unroll
        for (int k = 0; k < KN; ++k) if (row[k] != 0) kc = k;
        scls[tid] = kc;
    }

    int p = blk * 64 + tid;                // 0..32767
    int b0 = p, b1 = p + HB;

    // z pairs: zp[j] = (z0_j, z1_j); zp[32] = (1,1); zp[33] = (0,0)
    ull zp[34];
    #pragma unroll
    for (int i = 0; i < 8; ++i) {
        float4 v0 = ((const float4*)(data + (size_t)b0 * DN))[i];
        float4 v1 = ((const float4*)(data + (size_t)b1 * DN))[i];
        zp[4 * i + 0] = pack2(v0.x, v1.x);
        zp[4 * i + 1] = pack2(v0.y, v1.y);
        zp[4 * i + 2] = pack2(v0.z, v1.z);
        zp[4 * i + 3] = pack2(v0.w, v1.w);
    }
    zp[32] = pack2(1.f, 1.f);
    zp[33] = 0ull;

    unsigned sb0 = (unsigned)__cvta_generic_to_shared(&sbuf[0][0]);

    // stage first cluster of this half
    {
        const uint4* src = (const uint4*)(g_P2 + (size_t)cbase * CLBYTES);
        #pragma unroll
        for (int q = 0; q < 5; ++q) {
            int idx = tid + 64 * q;
            if (idx < NSLOT / 2) sbuf[0][idx] = src[idx];
        }
    }
    __syncthreads();

    float sc0[KN], sc1[KN];
    #pragma unroll
    for (int k = 0; k < KN; ++k) { sc0[k] = 0.f; sc1[k] = 0.f; }
    float gsum0 = 0.f, gbest0 = -1.f, gsum1 = 0.f, gbest1 = -1.f;
    int cbest0 = cbase, cbest1 = cbase;

    for (int cl = 0; cl < 64; ++cl) {
        int cur = cl & 1;

        // prefetch next cluster (L2 hit; hidden under the FMA block)
        uint4 st[5];
        bool pf = (cl + 1 < 64);
        if (pf) {
            const uint4* src = (const uint4*)(g_P2 + (size_t)(cbase + cl + 1) * CLBYTES);
            #pragma unroll
            for (int q = 0; q < 5; ++q) {
                int idx = tid + 64 * q;
                st[q] = (idx < NSLOT / 2) ? src[idx] : make_uint4(0, 0, 0, 0);
            }
        }

        unsigned base = sb0 + (unsigned)cur * (unsigned)CLBYTES;
        ull hq = 0ull;
        #pragma unroll
        for (int d = 0; d < 33; ++d) {
            const int nq = (34 - d) >> 1;        // compile-time (unrolled)
            const int off = rs2(d);
            ull a0 = 0ull, a1 = 0ull;
            #pragma unroll
            for (int q = 0; q < nq; ++q) {
                ull c0, c1;
                lds_v2b64(c0, c1, base + (unsigned)((off + 2 * q) * 8));
                a0 = fma2(c0, zp[d + 2 * q], a0);
                a1 = fma2(c1, zp[d + 2 * q + 1], a1);
            }
            a0 = add2(a0, a1);
            hq = fma2(zp[d], a0, hq);
        }

        float h0, h1;
        unpack2(hq, h0, h1);
        float g0 = __expf(-h0);
        float g1 = __expf(-h1);
        int cg = cbase + cl;
        gsum0 += g0; gsum1 += g1;
        if (g0 > gbest0) { gbest0 = g0; cbest0 = cg; }   // strict > == first-max
        if (g1 > gbest1) { gbest1 = g1; cbest1 = cg; }
        int kc = scls[cl];
        #pragma unroll
        for (int k = 0; k < KN; ++k)
            if (kc == k) { sc0[k] += g0; sc1[k] += g1; }

        if (pf) {
            #pragma unroll
            for (int q = 0; q < 5; ++q) {
                int idx = tid + 64 * q;
                if (idx < NSLOT / 2) sbuf[cur ^ 1][idx] = st[q];
            }
        }
        __syncthreads();
    }

    // write per-half partials (SoA, coalesced)
    #pragma unroll
    for (int k = 0; k < KN; ++k) {
        g_part[half][k][b0] = sc0[k];
        g_part[half][k][b1] = sc1[k];
    }
    g_part[half][10][b0] = gsum0;           g_part[half][10][b1] = gsum1;
    g_part[half][11][b0] = gbest0;          g_part[half][11][b1] = gbest1;
    g_part[half][12][b0] = (float)cbest0;   g_part[half][12][b1] = (float)cbest1;
}

// ---------------------------------------------------------------------------
// Combine: merge the two halves, normalize, argmax, write outputs.
// ---------------------------------------------------------------------------
__global__ __launch_bounds__(256)
void combine(float* __restrict__ out, int out_size) {
    int sb = blockIdx.x * 256 + threadIdx.x;   // 0..65535

    float gsum = g_part[0][10][sb] + g_part[1][10][sb];
    float inv = 1.f / (gsum + EPSV);

    float sbest = -1.f; int pbest = 0;
    float* os = out + (size_t)sb * KN;
    #pragma unroll
    for (int k = 0; k < KN; ++k) {
        float s = (g_part[0][k][sb] + g_part[1][k][sb]) * inv;
        os[k] = s;
        if (s > sbest) { sbest = s; pbest = k; }
    }

    float gb0 = g_part[0][11][sb], gb1 = g_part[1][11][sb];
    float cb = (gb1 > gb0) ? g_part[1][12][sb] : g_part[0][12][sb];  // half0 wins ties

    long bb = (long)BN * KN;
    if (out_size >= bb + BN)      out[bb + sb] = (float)pbest;
    if (out_size >= bb + 2 * BN)  out[bb + BN + sb] = cb;
}

extern "C" void kernel_launch(void* const* d_in, const int* in_sizes, int n_in,
                              void* d_out, int out_size) {
    const float* data   = (const float*)d_in[0];
    const float* mu     = (const float*)d_in[1];
    const float* S_inv  = (const float*)d_in[2];
    const int*   labels = (const int*)d_in[3];

    pre_kernel<<<CN, 128>>>(mu, S_inv);
    egauss2<<<1024, 64>>>(data, labels);
    combine<<<BN / 256, 256>>>((float*)d_out, out_size);
}

// round 7
// speedup vs baseline: 2.7610x; 1.5727x over previous
#include <cuda_runtime.h>
#include <cuda_bf16.h>
#include <cstdint>

#define BN 65536
#define CN 128
#define DN 32
#define KN 10
#define EPSV 1e-12f
#define NCH 36            // 576 features / 16 per chunk
#define ROWB 48           // padded row bytes: 16 bf16 (32B) + 16B pad (ldmatrix conflict-free)
#define SLAB 6144         // 128 rows * 48B, one split-chunk image

// Pre-split coefficient images: [split 0..2][chunk 0..35][row=cluster][48B]. 648 KB, L2-resident.
__device__ unsigned char g_Wb[3 * NCH * SLAB];

// ---- dynamic smem layout ----
#define SM_ZS   0                     // 128 samples * 33 floats (stride 33: conflict-free)
#define SM_LUT  16896                 // 576 uchar2
#define SM_SCLS 18048                 // 128 int
#define SM_A    18560                 // 3 * SLAB feature images
#define SM_B    (18560 + 3 * SLAB)    // 3 * SLAB coefficient images
#define SMEM_DYN (SM_B + 3 * SLAB)    // 55424 B

__device__ __forceinline__ uint32_t smem_u32(const void* p) {
    uint32_t a;
    asm("{ .reg .u64 t; cvta.to.shared.u64 t, %1; cvt.u32.u64 %0, t; }" : "=r"(a) : "l"(p));
    return a;
}
__device__ __forceinline__ void ldm_x4(uint32_t& r0, uint32_t& r1, uint32_t& r2, uint32_t& r3,
                                       uint32_t addr) {
    asm volatile("ldmatrix.sync.aligned.m8n8.x4.shared.b16 {%0,%1,%2,%3}, [%4];"
                 : "=r"(r0), "=r"(r1), "=r"(r2), "=r"(r3) : "r"(addr));
}
__device__ __forceinline__ void mma16816(float* d, const uint32_t* a, uint32_t b0, uint32_t b1) {
    asm volatile("mma.sync.aligned.m16n8k16.row.col.f32.bf16.bf16.f32 "
                 "{%0,%1,%2,%3}, {%4,%5,%6,%7}, {%8,%9}, {%0,%1,%2,%3};"
                 : "+f"(d[0]), "+f"(d[1]), "+f"(d[2]), "+f"(d[3])
                 : "r"(a[0]), "r"(a[1]), "r"(a[2]), "r"(a[3]), "r"(b0), "r"(b1));
}

// ---------------------------------------------------------------------------
// Pre-kernel: C_c[i,j] = Mext[i][j] * (i==j ? 0.5 : 1), Mext = [[W,-Wmu],[-mu'W,mu'Wmu]],
// triple-split to bf16 (h + m + l), written into the 3 chunked 48B-row images.
// ---------------------------------------------------------------------------
__global__ void pre_kernel(const float* __restrict__ mu,
                           const float* __restrict__ S_inv) {
    int c = blockIdx.x, t = threadIdx.x;
    __shared__ float sSm[DN];
    __shared__ float sT3;
    const float* W = S_inv + (size_t)c * DN * DN;
    const float* m = mu + (size_t)c * DN;

    if (t < DN) {
        float a = 0.f;
        #pragma unroll
        for (int e = 0; e < DN; ++e) a = fmaf(W[t * DN + e], m[e], a);
        sSm[t] = a;
    }
    __syncthreads();
    if (t == 0) {
        float a = 0.f;
        #pragma unroll
        for (int d = 0; d < DN; ++d) a = fmaf(m[d], sSm[d], a);
        sT3 = a;
    }
    __syncthreads();

    for (int k = t; k < 576; k += 128) {
        float Cv = 0.f;
        if (k < 561) {
            int i = 0;
            while (i < 32 && k >= 33 * (i + 1) - ((i + 1) * i) / 2) ++i;
            int j = i + (k - (33 * i - (i * (i - 1)) / 2));
            float Mv;
            if (j < 32)        Mv = W[i * DN + j];
            else if (i < 32)   Mv = -sSm[i];
            else               Mv = sT3;
            Cv = (i == j) ? 0.5f * Mv : Mv;
        }
        __nv_bfloat16 h = __float2bfloat16(Cv);
        float r1 = Cv - __bfloat162float(h);
        __nv_bfloat16 mm = __float2bfloat16(r1);
        float r2 = r1 - __bfloat162float(mm);
        __nv_bfloat16 l = __float2bfloat16(r2);

        size_t rowoff = (size_t)(k >> 4) * SLAB + (size_t)c * ROWB + (size_t)(k & 15) * 2;
        *(__nv_bfloat16*)(g_Wb + 0 * NCH * SLAB + rowoff) = h;
        *(__nv_bfloat16*)(g_Wb + 1 * NCH * SLAB + rowoff) = mm;
        *(__nv_bfloat16*)(g_Wb + 2 * NCH * SLAB + rowoff) = l;
    }
    // zero pad bytes 32..47 of this cluster's row in every image
    if (t < 108) {
        int sp = t / 36, ch = t - sp * 36;
        *(uint4*)(g_Wb + (size_t)(sp * NCH + ch) * SLAB + (size_t)c * ROWB + 32) =
            make_uint4(0, 0, 0, 0);
    }
}

// ---------------------------------------------------------------------------
// Main kernel: 512 CTAs x 256 threads. CTA tile = 128 samples x 128 clusters.
// K-loop: 36 chunks of 16 features, 6 split-product mma accumulations.
// ---------------------------------------------------------------------------
__global__ __launch_bounds__(256, 2)
void egauss_hmma(const float* __restrict__ data,
                 const int* __restrict__ labels,
                 float* __restrict__ out,
                 int out_size) {
    extern __shared__ char smem[];
    float* zs = (float*)(smem + SM_ZS);
    uchar2* lut = (uchar2*)(smem + SM_LUT);
    int* scls = (int*)(smem + SM_SCLS);
    uint32_t sb = smem_u32(smem);

    int tid = threadIdx.x;
    int wid = tid >> 5, lane = tid & 31;

    // feature (i,j) LUT; pad features k>=561 -> (0,0) (product * 0-coeff = 0, finite)
    for (int k = tid; k < 576; k += 256) {
        int i = 0, j = 0;
        if (k < 561) {
            while (i < 32 && k >= 33 * (i + 1) - ((i + 1) * i) / 2) ++i;
            j = i + (k - (33 * i - (i * (i - 1)) / 2));
        }
        lut[k] = make_uchar2((unsigned char)i, (unsigned char)j);
    }
    if (tid < CN) {
        const int* row = labels + tid * KN;
        int kc = 0;
        #pragma unroll
        for (int k = 0; k < KN; ++k) if (row[k] != 0) kc = k;
        scls[tid] = kc;
    }
    // stage z tile: 128 samples x 32 floats (+1), stride 33
    {
        int s = tid >> 1, hf = tid & 1;
        const float4* src = (const float4*)(data + ((size_t)blockIdx.x * 128 + s) * DN + hf * 16);
        #pragma unroll
        for (int q = 0; q < 4; ++q) {
            float4 v = src[q];
            float* dst = zs + s * 33 + hf * 16 + q * 4;
            dst[0] = v.x; dst[1] = v.y; dst[2] = v.z; dst[3] = v.w;
        }
        if (tid < 128) zs[tid * 33 + 32] = 1.f;
    }

    float acc[16][4];
    #pragma unroll
    for (int n = 0; n < 16; ++n)
        #pragma unroll
        for (int q = 0; q < 4; ++q) acc[n][q] = 0.f;

    int s = tid >> 1, hf = tid & 1;
    const float* zrow = zs + s * 33;

    // ldmatrix source addresses (A: per-warp 16 rows; B: per n-tile-pair)
    uint32_t a_row = (uint32_t)(wid * 16 + (lane & 15));
    uint32_t a_colb = (uint32_t)((lane >> 4) * 16);
    uint32_t aAddr = sb + SM_A + a_row * ROWB + a_colb;
    uint32_t b_row = (uint32_t)((lane & 7) + ((lane & 16) ? 8 : 0));
    uint32_t b_colb = (uint32_t)((lane & 8) ? 16 : 0);

    for (int ch = 0; ch < NCH; ++ch) {
        __syncthreads();   // previous chunk's mma reads done

        // copy coefficient chunk (3 splits, contiguous 6KB slabs)
        #pragma unroll
        for (int sp = 0; sp < 3; ++sp) {
            const uint4* src = (const uint4*)(g_Wb + (size_t)(sp * NCH + ch) * SLAB);
            uint4* dst = (uint4*)(smem + SM_B + sp * SLAB);
            for (int idx = tid; idx < SLAB / 16; idx += 256) dst[idx] = src[idx];
        }

        // build 8 features (triple-split) for this thread's half-row
        {
            int kb = ch * 16 + hf * 8;
            unsigned hw[8], mw[8], lw[8];
            #pragma unroll
            for (int q = 0; q < 8; ++q) {
                uchar2 p = lut[kb + q];
                float f = zrow[p.x] * zrow[p.y];
                __nv_bfloat16 h = __float2bfloat16(f);
                float r1 = f - __bfloat162float(h);
                __nv_bfloat16 mm = __float2bfloat16(r1);
                float r2 = r1 - __bfloat162float(mm);
                __nv_bfloat16 l = __float2bfloat16(r2);
                hw[q] = __bfloat16_as_ushort(h);
                mw[q] = __bfloat16_as_ushort(mm);
                lw[q] = __bfloat16_as_ushort(l);
            }
            unsigned off = (unsigned)(s * ROWB + hf * 16);
            *(uint4*)(smem + SM_A + 0 * SLAB + off) =
                make_uint4(hw[0] | (hw[1] << 16), hw[2] | (hw[3] << 16),
                           hw[4] | (hw[5] << 16), hw[6] | (hw[7] << 16));
            *(uint4*)(smem + SM_A + 1 * SLAB + off) =
                make_uint4(mw[0] | (mw[1] << 16), mw[2] | (mw[3] << 16),
                           mw[4] | (mw[5] << 16), mw[6] | (mw[7] << 16));
            *(uint4*)(smem + SM_A + 2 * SLAB + off) =
                make_uint4(lw[0] | (lw[1] << 16), lw[2] | (lw[3] << 16),
                           lw[4] | (lw[5] << 16), lw[6] | (lw[7] << 16));
        }
        __syncthreads();

        // A fragments for the 3 splits
        uint32_t ah[4], am[4], al[4];
        ldm_x4(ah[0], ah[1], ah[2], ah[3], aAddr + 0 * SLAB);
        ldm_x4(am[0], am[1], am[2], am[3], aAddr + 1 * SLAB);
        ldm_x4(al[0], al[1], al[2], al[3], aAddr + 2 * SLAB);

        #pragma unroll
        for (int nt2 = 0; nt2 < 8; ++nt2) {
            uint32_t bAddr = sb + SM_B + (nt2 * 16 + b_row) * ROWB + b_colb;
            uint32_t bh[4], bm[4], bl[4];
            ldm_x4(bh[0], bh[1], bh[2], bh[3], bAddr + 0 * SLAB);
            ldm_x4(bm[0], bm[1], bm[2], bm[3], bAddr + 1 * SLAB);
            ldm_x4(bl[0], bl[1], bl[2], bl[3], bAddr + 2 * SLAB);

            float* d0 = acc[2 * nt2];
            float* d1 = acc[2 * nt2 + 1];
            // 6-product pyramid: hh, mh, hm, lh, mm, hl
            mma16816(d0, ah, bh[0], bh[1]);  mma16816(d1, ah, bh[2], bh[3]);
            mma16816(d0, am, bh[0], bh[1]);  mma16816(d1, am, bh[2], bh[3]);
            mma16816(d0, ah, bm[0], bm[1]);  mma16816(d1, ah, bm[2], bm[3]);
            mma16816(d0, al, bh[0], bh[1]);  mma16816(d1, al, bh[2], bh[3]);
            mma16816(d0, am, bm[0], bm[1]);  mma16816(d1, am, bm[2], bm[3]);
            mma16816(d0, ah, bl[0], bl[1]);  mma16816(d1, ah, bl[2], bl[3]);
        }
    }

    // ---- epilogue: lane holds rows {rA, rA+8}, cols c = nt*8 + 2q + {0,1} ----
    int q = lane & 3, rA = lane >> 2;
    float scA[KN], scB[KN];
    #pragma unroll
    for (int k = 0; k < KN; ++k) { scA[k] = 0.f; scB[k] = 0.f; }
    float gsumA = 0.f, gsumB = 0.f, bestA = -1.f, bestB = -1.f;
    int cbA = 0, cbB = 0;

    #pragma unroll
    for (int nt = 0; nt < 16; ++nt) {
        int c0 = nt * 8 + q * 2;
        float gA0 = __expf(-acc[nt][0]);
        float gA1 = __expf(-acc[nt][1]);
        float gB0 = __expf(-acc[nt][2]);
        float gB1 = __expf(-acc[nt][3]);
        gsumA += gA0 + gA1;  gsumB += gB0 + gB1;
        if (gA0 > bestA) { bestA = gA0; cbA = c0; }
        if (gA1 > bestA) { bestA = gA1; cbA = c0 + 1; }
        if (gB0 > bestB) { bestB = gB0; cbB = c0; }
        if (gB1 > bestB) { bestB = gB1; cbB = c0 + 1; }
        int k0 = scls[c0], k1 = scls[c0 + 1];
        #pragma unroll
        for (int k = 0; k < KN; ++k) {
            if (k0 == k) { scA[k] += gA0; scB[k] += gB0; }
            if (k1 == k) { scA[k] += gA1; scB[k] += gB1; }
        }
    }

    // quad reduction (lanes sharing a row: xor 1, 2); first-max tie rule on index
    #pragma unroll
    for (int d = 1; d <= 2; d <<= 1) {
        gsumA += __shfl_xor_sync(0xffffffffu, gsumA, d);
        gsumB += __shfl_xor_sync(0xffffffffu, gsumB, d);
        #pragma unroll
        for (int k = 0; k < KN; ++k) {
            scA[k] += __shfl_xor_sync(0xffffffffu, scA[k], d);
            scB[k] += __shfl_xor_sync(0xffffffffu, scB[k], d);
        }
        float obA = __shfl_xor_sync(0xffffffffu, bestA, d);
        int ocA = __shfl_xor_sync(0xffffffffu, cbA, d);
        if (obA > bestA || (obA == bestA && ocA < cbA)) { bestA = obA; cbA = ocA; }
        float obB = __shfl_xor_sync(0xffffffffu, bestB, d);
        int ocB = __shfl_xor_sync(0xffffffffu, cbB, d);
        if (obB > bestB || (obB == bestB && ocB < cbB)) { bestB = obB; cbB = ocB; }
    }

    if (q == 0) {
        long bb = (long)BN * KN;
        {
            long b = (long)blockIdx.x * 128 + wid * 16 + rA;
            float inv = 1.f / (gsumA + EPSV);
            float sb2 = -1.f; int pb = 0;
            float* os = out + b * KN;
            #pragma unroll
            for (int k = 0; k < KN; ++k) {
                float sv = scA[k] * inv;
                os[k] = sv;
                if (sv > sb2) { sb2 = sv; pb = k; }
            }
            if (out_size >= bb + BN)      out[bb + b] = (float)pb;
            if (out_size >= bb + 2 * BN)  out[bb + BN + b] = (float)cbA;
        }
        {
            long b = (long)blockIdx.x * 128 + wid * 16 + rA + 8;
            float inv = 1.f / (gsumB + EPSV);
            float sb2 = -1.f; int pb = 0;
            float* os = out + b * KN;
            #pragma unroll
            for (int k = 0; k < KN; ++k) {
                float sv = scB[k] * inv;
                os[k] = sv;
                if (sv > sb2) { sb2 = sv; pb = k; }
            }
            if (out_size >= bb + BN)      out[bb + b] = (float)pb;
            if (out_size >= bb + 2 * BN)  out[bb + BN + b] = (float)cbB;
        }
    }
}

extern "C" void kernel_launch(void* const* d_in, const int* in_sizes, int n_in,
                              void* d_out, int out_size) {
    const float* data   = (const float*)d_in[0];
    const float* mu     = (const float*)d_in[1];
    const float* S_inv  = (const float*)d_in[2];
    const int*   labels = (const int*)d_in[3];

    cudaFuncSetAttribute(egauss_hmma, cudaFuncAttributeMaxDynamicSharedMemorySize, SMEM_DYN);
    pre_kernel<<<CN, 128>>>(mu, S_inv);
    egauss_hmma<<<BN / 128, 256, SMEM_DYN>>>(data, labels, (float*)d_out, out_size);
}

// round 8
// speedup vs baseline: 3.6853x; 1.3348x over previous
#include <cuda_runtime.h>
#include <cuda_bf16.h>
#include <cstdint>

#define BN 65536
#define CN 128
#define DN 32
#define KN 10
#define EPSV 1e-12f
#define NCH 36            // 576 features / 16 per chunk
#define ROWB 48           // padded row bytes: 16 bf16 (32B) + 16B pad (ldmatrix conflict-free)
#define SLAB 6144         // 128 rows * 48B, one split-chunk image
#define SLAB3 18432       // 3 splits

// Pre-split coefficient images: [split 0..2][chunk 0..35][row=cluster][48B]. 648 KB, L2-resident.
__device__ unsigned char g_Wb[3 * NCH * SLAB];

// ---- dynamic smem layout ----
#define SM_ZS   0                     // 128 samples * 33 floats (stride 33)
#define SM_LUT  16896                 // 576 uchar2
#define SM_SCLS 18048                 // 128 int
#define SM_A    18560                 // 2 buffers x 3*SLAB feature images
#define SM_B    (SM_A + 2 * SLAB3)    // 2 buffers x 3*SLAB coefficient images
#define SMEM_DYN (SM_B + 2 * SLAB3)   // 92288 B

__device__ __forceinline__ uint32_t smem_u32(const void* p) {
    uint32_t a;
    asm("{ .reg .u64 t; cvta.to.shared.u64 t, %1; cvt.u32.u64 %0, t; }" : "=r"(a) : "l"(p));
    return a;
}
__device__ __forceinline__ void ldm_x4(uint32_t& r0, uint32_t& r1, uint32_t& r2, uint32_t& r3,
                                       uint32_t addr) {
    asm volatile("ldmatrix.sync.aligned.m8n8.x4.shared.b16 {%0,%1,%2,%3}, [%4];"
                 : "=r"(r0), "=r"(r1), "=r"(r2), "=r"(r3) : "r"(addr));
}
__device__ __forceinline__ void mma16816(float* d, const uint32_t* a, uint32_t b0, uint32_t b1) {
    asm volatile("mma.sync.aligned.m16n8k16.row.col.f32.bf16.bf16.f32 "
                 "{%0,%1,%2,%3}, {%4,%5,%6,%7}, {%8,%9}, {%0,%1,%2,%3};"
                 : "+f"(d[0]), "+f"(d[1]), "+f"(d[2]), "+f"(d[3])
                 : "r"(a[0]), "r"(a[1]), "r"(a[2]), "r"(a[3]), "r"(b0), "r"(b1));
}
__device__ __forceinline__ void cpasync16(uint32_t dst, const void* src) {
    asm volatile("cp.async.cg.shared.global [%0], [%1], 16;" :: "r"(dst), "l"(src));
}
#define CP_COMMIT() asm volatile("cp.async.commit_group;" ::: "memory")
#define CP_WAIT0()  asm volatile("cp.async.wait_group 0;" ::: "memory")

// ---------------------------------------------------------------------------
// Pre-kernel: C_c[i,j] = Mext[i][j] * (i==j ? 0.5 : 1), triple-split to bf16.
// ---------------------------------------------------------------------------
__global__ void pre_kernel(const float* __restrict__ mu,
                           const float* __restrict__ S_inv) {
    int c = blockIdx.x, t = threadIdx.x;
    __shared__ float sSm[DN];
    __shared__ float sT3;
    const float* W = S_inv + (size_t)c * DN * DN;
    const float* m = mu + (size_t)c * DN;

    if (t < DN) {
        float a = 0.f;
        #pragma unroll
        for (int e = 0; e < DN; ++e) a = fmaf(W[t * DN + e], m[e], a);
        sSm[t] = a;
    }
    __syncthreads();
    if (t == 0) {
        float a = 0.f;
        #pragma unroll
        for (int d = 0; d < DN; ++d) a = fmaf(m[d], sSm[d], a);
        sT3 = a;
    }
    __syncthreads();

    for (int k = t; k < 576; k += 128) {
        float Cv = 0.f;
        if (k < 561) {
            int i = 0;
            while (i < 32 && k >= 33 * (i + 1) - ((i + 1) * i) / 2) ++i;
            int j = i + (k - (33 * i - (i * (i - 1)) / 2));
            float Mv;
            if (j < 32)        Mv = W[i * DN + j];
            else if (i < 32)   Mv = -sSm[i];
            else               Mv = sT3;
            Cv = (i == j) ? 0.5f * Mv : Mv;
        }
        __nv_bfloat16 h = __float2bfloat16(Cv);
        float r1 = Cv - __bfloat162float(h);
        __nv_bfloat16 mm = __float2bfloat16(r1);
        float r2 = r1 - __bfloat162float(mm);
        __nv_bfloat16 l = __float2bfloat16(r2);

        size_t rowoff = (size_t)(k >> 4) * SLAB + (size_t)c * ROWB + (size_t)(k & 15) * 2;
        *(__nv_bfloat16*)(g_Wb + 0 * NCH * SLAB + rowoff) = h;
        *(__nv_bfloat16*)(g_Wb + 1 * NCH * SLAB + rowoff) = mm;
        *(__nv_bfloat16*)(g_Wb + 2 * NCH * SLAB + rowoff) = l;
    }
    if (t < 108) {
        int sp = t / 36, ch = t - sp * 36;
        *(uint4*)(g_Wb + (size_t)(sp * NCH + ch) * SLAB + (size_t)c * ROWB + 32) =
            make_uint4(0, 0, 0, 0);
    }
}

// ---------------------------------------------------------------------------
// Main kernel: 512 CTAs x 256 threads; double-buffered, cp.async-pipelined.
// ---------------------------------------------------------------------------
__global__ __launch_bounds__(256, 2)
void egauss_hmma(const float* __restrict__ data,
                 const int* __restrict__ labels,
                 float* __restrict__ out,
                 int out_size) {
    extern __shared__ char smem[];
    float* zs = (float*)(smem + SM_ZS);
    uchar2* lut = (uchar2*)(smem + SM_LUT);
    int* scls = (int*)(smem + SM_SCLS);
    uint32_t sb = smem_u32(smem);

    int tid = threadIdx.x;
    int wid = tid >> 5, lane = tid & 31;
    int s = tid >> 1, hf = tid & 1;

    // feature (i,j) LUT; pad features k>=561 -> (0,0)
    for (int k = tid; k < 576; k += 256) {
        int i = 0, j = 0;
        if (k < 561) {
            while (i < 32 && k >= 33 * (i + 1) - ((i + 1) * i) / 2) ++i;
            j = i + (k - (33 * i - (i * (i - 1)) / 2));
        }
        lut[k] = make_uchar2((unsigned char)i, (unsigned char)j);
    }
    if (tid < CN) {
        const int* row = labels + tid * KN;
        int kc = 0;
        #pragma unroll
        for (int k = 0; k < KN; ++k) if (row[k] != 0) kc = k;
        scls[tid] = kc;
    }
    // stage z tile: 128 samples x (32+1) floats, stride 33
    {
        const float4* src = (const float4*)(data + ((size_t)blockIdx.x * 128 + s) * DN + hf * 16);
        #pragma unroll
        for (int q = 0; q < 4; ++q) {
            float4 v = src[q];
            float* dst = zs + s * 33 + hf * 16 + q * 4;
            dst[0] = v.x; dst[1] = v.y; dst[2] = v.z; dst[3] = v.w;
        }
        if (tid < 128) zs[tid * 33 + 32] = 1.f;
    }
    __syncthreads();   // zs/lut ready for feature build

    const float* zrow = zs + s * 33;

    // ---- pipeline helpers (macros keep everything in-scope) ----
#define COPY_B(CHI, BUF)                                                          \
    {                                                                             \
        _Pragma("unroll")                                                         \
        for (int sp = 0; sp < 3; ++sp) {                                          \
            const unsigned char* gsrc = g_Wb + (size_t)(sp * NCH + (CHI)) * SLAB; \
            uint32_t dbase = sb + SM_B + (BUF) * SLAB3 + sp * SLAB;               \
            _Pragma("unroll")                                                     \
            for (int r = 0; r < 2; ++r) {                                         \
                int idx = tid + 256 * r;                                          \
                if (idx < SLAB / 16)                                              \
                    cpasync16(dbase + (uint32_t)(idx * 16), gsrc + idx * 16);     \
            }                                                                     \
        }                                                                         \
        CP_COMMIT();                                                              \
    }

#define BUILD_A(CHI, BUF)                                                         \
    {                                                                             \
        int kb = (CHI) * 16 + hf * 8;                                             \
        unsigned hw[8], mw[8], lw[8];                                             \
        _Pragma("unroll")                                                         \
        for (int q = 0; q < 8; ++q) {                                             \
            uchar2 p = lut[kb + q];                                               \
            float f = zrow[p.x] * zrow[p.y];                                      \
            __nv_bfloat16 h = __float2bfloat16(f);                                \
            float r1 = f - __bfloat162float(h);                                   \
            __nv_bfloat16 mmv = __float2bfloat16(r1);                             \
            float r2 = r1 - __bfloat162float(mmv);                                \
            __nv_bfloat16 l = __float2bfloat16(r2);                               \
            hw[q] = __bfloat16_as_ushort(h);                                      \
            mw[q] = __bfloat16_as_ushort(mmv);                                    \
            lw[q] = __bfloat16_as_ushort(l);                                      \
        }                                                                         \
        unsigned off = (unsigned)((BUF) * SLAB3 + s * ROWB + hf * 16);            \
        *(uint4*)(smem + SM_A + 0 * SLAB + off) =                                 \
            make_uint4(hw[0] | (hw[1] << 16), hw[2] | (hw[3] << 16),              \
                       hw[4] | (hw[5] << 16), hw[6] | (hw[7] << 16));             \
        *(uint4*)(smem + SM_A + 1 * SLAB + off) =                                 \
            make_uint4(mw[0] | (mw[1] << 16), mw[2] | (mw[3] << 16),              \
                       mw[4] | (mw[5] << 16), mw[6] | (mw[7] << 16));             \
        *(uint4*)(smem + SM_A + 2 * SLAB + off) =                                 \
            make_uint4(lw[0] | (lw[1] << 16), lw[2] | (lw[3] << 16),              \
                       lw[4] | (lw[5] << 16), lw[6] | (lw[7] << 16));             \
    }

    float acc[16][4];
    #pragma unroll
    for (int n = 0; n < 16; ++n)
        #pragma unroll
        for (int q = 0; q < 4; ++q) acc[n][q] = 0.f;

    // ldmatrix source addresses
    uint32_t a_row = (uint32_t)(wid * 16 + (lane & 15));
    uint32_t a_colb = (uint32_t)((lane >> 4) * 16);
    uint32_t b_row = (uint32_t)((lane & 7) + ((lane & 16) ? 8 : 0));
    uint32_t b_colb = (uint32_t)((lane & 8) ? 16 : 0);

    // prologue: chunk 0 into buffer 0
    COPY_B(0, 0)
    BUILD_A(0, 0)
    CP_WAIT0();
    __syncthreads();

    for (int ch = 0; ch < NCH; ++ch) {
        int cur = ch & 1, nxt = cur ^ 1;

        // start next chunk's coefficient copy (async, no reg staging)
        if (ch + 1 < NCH) COPY_B(ch + 1, nxt)

        uint32_t aAddr = sb + SM_A + (uint32_t)(cur * SLAB3) + a_row * ROWB + a_colb;
        uint32_t ah[4], am[4], al[4];
        ldm_x4(ah[0], ah[1], ah[2], ah[3], aAddr + 0 * SLAB);
        ldm_x4(am[0], am[1], am[2], am[3], aAddr + 1 * SLAB);
        ldm_x4(al[0], al[1], al[2], al[3], aAddr + 2 * SLAB);

        #pragma unroll
        for (int nt2 = 0; nt2 < 8; ++nt2) {
            uint32_t bAddr = sb + SM_B + (uint32_t)(cur * SLAB3)
                           + (nt2 * 16 + b_row) * ROWB + b_colb;
            uint32_t bh[4], bm[4], bl[4];
            ldm_x4(bh[0], bh[1], bh[2], bh[3], bAddr + 0 * SLAB);
            ldm_x4(bm[0], bm[1], bm[2], bm[3], bAddr + 1 * SLAB);
            ldm_x4(bl[0], bl[1], bl[2], bl[3], bAddr + 2 * SLAB);

            float* d0 = acc[2 * nt2];
            float* d1 = acc[2 * nt2 + 1];
            mma16816(d0, ah, bh[0], bh[1]);  mma16816(d1, ah, bh[2], bh[3]);
            mma16816(d0, am, bh[0], bh[1]);  mma16816(d1, am, bh[2], bh[3]);
            mma16816(d0, ah, bm[0], bm[1]);  mma16816(d1, ah, bm[2], bm[3]);
            mma16816(d0, al, bh[0], bh[1]);  mma16816(d1, al, bh[2], bh[3]);
            mma16816(d0, am, bm[0], bm[1]);  mma16816(d1, am, bm[2], bm[3]);
            mma16816(d0, ah, bl[0], bl[1]);  mma16816(d1, ah, bl[2], bl[3]);
        }

        // build next chunk's features into the other buffer (no barrier needed:
        // different buffer than the one being read by this chunk's ldmatrix)
        if (ch + 1 < NCH) BUILD_A(ch + 1, nxt)

        CP_WAIT0();
        __syncthreads();   // next buffer fully visible; cur buffer free for ch+2
    }
#undef COPY_B
#undef BUILD_A

    // ---- epilogue: lane holds rows {rA, rA+8}, cols c = nt*8 + 2q + {0,1} ----
    int q = lane & 3, rA = lane >> 2;
    float scA[KN], scB[KN];
    #pragma unroll
    for (int k = 0; k < KN; ++k) { scA[k] = 0.f; scB[k] = 0.f; }
    float gsumA = 0.f, gsumB = 0.f, bestA = -1.f, bestB = -1.f;
    int cbA = 0, cbB = 0;

    #pragma unroll
    for (int nt = 0; nt < 16; ++nt) {
        int c0 = nt * 8 + q * 2;
        float gA0 = __expf(-acc[nt][0]);
        float gA1 = __expf(-acc[nt][1]);
        float gB0 = __expf(-acc[nt][2]);
        float gB1 = __expf(-acc[nt][3]);
        gsumA += gA0 + gA1;  gsumB += gB0 + gB1;
        if (gA0 > bestA) { bestA = gA0; cbA = c0; }
        if (gA1 > bestA) { bestA = gA1; cbA = c0 + 1; }
        if (gB0 > bestB) { bestB = gB0; cbB = c0; }
        if (gB1 > bestB) { bestB = gB1; cbB = c0 + 1; }
        int k0 = scls[c0], k1 = scls[c0 + 1];
        #pragma unroll
        for (int k = 0; k < KN; ++k) {
            if (k0 == k) { scA[k] += gA0; scB[k] += gB0; }
            if (k1 == k) { scA[k] += gA1; scB[k] += gB1; }
        }
    }

    #pragma unroll
    for (int d = 1; d <= 2; d <<= 1) {
        gsumA += __shfl_xor_sync(0xffffffffu, gsumA, d);
        gsumB += __shfl_xor_sync(0xffffffffu, gsumB, d);
        #pragma unroll
        for (int k = 0; k < KN; ++k) {
            scA[k] += __shfl_xor_sync(0xffffffffu, scA[k], d);
            scB[k] += __shfl_xor_sync(0xffffffffu, scB[k], d);
        }
        float obA = __shfl_xor_sync(0xffffffffu, bestA, d);
        int ocA = __shfl_xor_sync(0xffffffffu, cbA, d);
        if (obA > bestA || (obA == bestA && ocA < cbA)) { bestA = obA; cbA = ocA; }
        float obB = __shfl_xor_sync(0xffffffffu, bestB, d);
        int ocB = __shfl_xor_sync(0xffffffffu, cbB, d);
        if (obB > bestB || (obB == bestB && ocB < cbB)) { bestB = obB; cbB = ocB; }
    }

    if (q == 0) {
        long bb = (long)BN * KN;
        {
            long b = (long)blockIdx.x * 128 + wid * 16 + rA;
            float inv = 1.f / (gsumA + EPSV);
            float sb2 = -1.f; int pb = 0;
            float* os = out + b * KN;
            #pragma unroll
            for (int k = 0; k < KN; ++k) {
                float sv = scA[k] * inv;
                os[k] = sv;
                if (sv > sb2) { sb2 = sv; pb = k; }
            }
            if (out_size >= bb + BN)      out[bb + b] = (float)pb;
            if (out_size >= bb + 2 * BN)  out[bb + BN + b] = (float)cbA;
        }
        {
            long b = (long)blockIdx.x * 128 + wid * 16 + rA + 8;
            float inv = 1.f / (gsumB + EPSV);
            float sb2 = -1.f; int pb = 0;
            float* os = out + b * KN;
            #pragma unroll
            for (int k = 0; k < KN; ++k) {
                float sv = scB[k] * inv;
                os[k] = sv;
                if (sv > sb2) { sb2 = sv; pb = k; }
            }
            if (out_size >= bb + BN)      out[bb + b] = (float)pb;
            if (out_size >= bb + 2 * BN)  out[bb + BN + b] = (float)cbB;
        }
    }
}

extern "C" void kernel_launch(void* const* d_in, const int* in_sizes, int n_in,
                              void* d_out, int out_size) {
    const float* data   = (const float*)d_in[0];
    const float* mu     = (const float*)d_in[1];
    const float* S_inv  = (const float*)d_in[2];
    const int*   labels = (const int*)d_in[3];

    cudaFuncSetAttribute(egauss_hmma, cudaFuncAttributeMaxDynamicSharedMemorySize, SMEM_DYN);
    pre_kernel<<<CN, 128>>>(mu, S_inv);
    egauss_hmma<<<BN / 128, 256, SMEM_DYN>>>(data, labels, (float*)d_out, out_size);
}

// round 9
// speedup vs baseline: 5.7556x; 1.5618x over previous
#include <cuda_runtime.h>
#include <cuda_fp16.h>
#include <cstdint>

#define BN 65536
#define CN 128
#define DN 32
#define KN 10
#define EPSV 1e-12f
#define NCH 36            // 576 features / 16 per chunk
#define ROWB 48           // padded row bytes: 16 fp16 (32B) + 16B pad (ldmatrix conflict-free)
#define SLAB 6144         // 128 rows * 48B, one split-chunk image
#define SLAB2 12288       // 2 splits

// Pre-split coefficient images: [split 0..1][chunk 0..35][row=cluster][48B]. 432 KB, L2-resident.
__device__ unsigned char g_Wb[2 * NCH * SLAB];

// ---- dynamic smem layout ----
#define SM_ZS   0                     // 128 samples * 33 floats (stride 33)
#define SM_LUT  16896                 // 576 uchar2
#define SM_SCLS 18048                 // 128 int
#define SM_A    18560                 // 2 buffers x 2*SLAB feature images
#define SM_B    (SM_A + 2 * SLAB2)    // 2 buffers x 2*SLAB coefficient images
#define SMEM_DYN (SM_B + 2 * SLAB2)   // 67712 B

__device__ __forceinline__ uint32_t smem_u32(const void* p) {
    uint32_t a;
    asm("{ .reg .u64 t; cvta.to.shared.u64 t, %1; cvt.u32.u64 %0, t; }" : "=r"(a) : "l"(p));
    return a;
}
__device__ __forceinline__ void ldm_x4(uint32_t& r0, uint32_t& r1, uint32_t& r2, uint32_t& r3,
                                       uint32_t addr) {
    asm volatile("ldmatrix.sync.aligned.m8n8.x4.shared.b16 {%0,%1,%2,%3}, [%4];"
                 : "=r"(r0), "=r"(r1), "=r"(r2), "=r"(r3) : "r"(addr));
}
__device__ __forceinline__ void mma16816(float* d, const uint32_t* a, uint32_t b0, uint32_t b1) {
    asm volatile("mma.sync.aligned.m16n8k16.row.col.f32.f16.f16.f32 "
                 "{%0,%1,%2,%3}, {%4,%5,%6,%7}, {%8,%9}, {%0,%1,%2,%3};"
                 : "+f"(d[0]), "+f"(d[1]), "+f"(d[2]), "+f"(d[3])
                 : "r"(a[0]), "r"(a[1]), "r"(a[2]), "r"(a[3]), "r"(b0), "r"(b1));
}
__device__ __forceinline__ void cpasync16(uint32_t dst, const void* src) {
    asm volatile("cp.async.cg.shared.global [%0], [%1], 16;" :: "r"(dst), "l"(src));
}
#define CP_COMMIT() asm volatile("cp.async.commit_group;" ::: "memory")
#define CP_WAIT0()  asm volatile("cp.async.wait_group 0;" ::: "memory")

// ---------------------------------------------------------------------------
// Pre-kernel: C_c[i,j] = Mext[i][j] * (i==j ? 0.5 : 1), 2-way fp16 split (h + l).
// ---------------------------------------------------------------------------
__global__ void pre_kernel(const float* __restrict__ mu,
                           const float* __restrict__ S_inv) {
    int c = blockIdx.x, t = threadIdx.x;
    __shared__ float sSm[DN];
    __shared__ float sT3;
    const float* W = S_inv + (size_t)c * DN * DN;
    const float* m = mu + (size_t)c * DN;

    if (t < DN) {
        float a = 0.f;
        #pragma unroll
        for (int e = 0; e < DN; ++e) a = fmaf(W[t * DN + e], m[e], a);
        sSm[t] = a;
    }
    __syncthreads();
    if (t == 0) {
        float a = 0.f;
        #pragma unroll
        for (int d = 0; d < DN; ++d) a = fmaf(m[d], sSm[d], a);
        sT3 = a;
    }
    __syncthreads();

    for (int k = t; k < 576; k += 128) {
        float Cv = 0.f;
        if (k < 561) {
            int i = 0;
            while (i < 32 && k >= 33 * (i + 1) - ((i + 1) * i) / 2) ++i;
            int j = i + (k - (33 * i - (i * (i - 1)) / 2));
            float Mv;
            if (j < 32)        Mv = W[i * DN + j];
            else if (i < 32)   Mv = -sSm[i];
            else               Mv = sT3;
            Cv = (i == j) ? 0.5f * Mv : Mv;
        }
        __half h = __float2half_rn(Cv);
        float r1 = Cv - __half2float(h);
        __half l = __float2half_rn(r1);

        size_t rowoff = (size_t)(k >> 4) * SLAB + (size_t)c * ROWB + (size_t)(k & 15) * 2;
        *(__half*)(g_Wb + 0 * NCH * SLAB + rowoff) = h;
        *(__half*)(g_Wb + 1 * NCH * SLAB + rowoff) = l;
    }
    if (t < 72) {
        int sp = t / 36, ch = t - sp * 36;
        *(uint4*)(g_Wb + (size_t)(sp * NCH + ch) * SLAB + (size_t)c * ROWB + 32) =
            make_uint4(0, 0, 0, 0);
    }
}

// ---------------------------------------------------------------------------
// Main kernel: 512 CTAs x 256 threads; fp16 2-split, 3-product pyramid,
// double-buffered with cp.async.
// ---------------------------------------------------------------------------
__global__ __launch_bounds__(256, 2)
void egauss_hmma(const float* __restrict__ data,
                 const int* __restrict__ labels,
                 float* __restrict__ out,
                 int out_size) {
    extern __shared__ char smem[];
    float* zs = (float*)(smem + SM_ZS);
    uchar2* lut = (uchar2*)(smem + SM_LUT);
    int* scls = (int*)(smem + SM_SCLS);
    uint32_t sb = smem_u32(smem);

    int tid = threadIdx.x;
    int wid = tid >> 5, lane = tid & 31;
    int s = tid >> 1, hf = tid & 1;

    // feature (i,j) LUT; pad features k>=561 -> (0,0)
    for (int k = tid; k < 576; k += 256) {
        int i = 0, j = 0;
        if (k < 561) {
            while (i < 32 && k >= 33 * (i + 1) - ((i + 1) * i) / 2) ++i;
            j = i + (k - (33 * i - (i * (i - 1)) / 2));
        }
        lut[k] = make_uchar2((unsigned char)i, (unsigned char)j);
    }
    if (tid < CN) {
        const int* row = labels + tid * KN;
        int kc = 0;
        #pragma unroll
        for (int k = 0; k < KN; ++k) if (row[k] != 0) kc = k;
        scls[tid] = kc;
    }
    // stage z tile: 128 samples x (32+1) floats, stride 33
    {
        const float4* src = (const float4*)(data + ((size_t)blockIdx.x * 128 + s) * DN + hf * 16);
        #pragma unroll
        for (int q = 0; q < 4; ++q) {
            float4 v = src[q];
            float* dst = zs + s * 33 + hf * 16 + q * 4;
            dst[0] = v.x; dst[1] = v.y; dst[2] = v.z; dst[3] = v.w;
        }
        if (tid < 128) zs[tid * 33 + 32] = 1.f;
    }
    __syncthreads();   // zs/lut ready for feature build

    const float* zrow = zs + s * 33;

#define COPY_B(CHI, BUF)                                                          \
    {                                                                             \
        _Pragma("unroll")                                                         \
        for (int sp = 0; sp < 2; ++sp) {                                          \
            const unsigned char* gsrc = g_Wb + (size_t)(sp * NCH + (CHI)) * SLAB; \
            uint32_t dbase = sb + SM_B + (BUF) * SLAB2 + sp * SLAB;               \
            _Pragma("unroll")                                                     \
            for (int r = 0; r < 2; ++r) {                                         \
                int idx = tid + 256 * r;                                          \
                if (idx < SLAB / 16)                                              \
                    cpasync16(dbase + (uint32_t)(idx * 16), gsrc + idx * 16);     \
            }                                                                     \
        }                                                                         \
        CP_COMMIT();                                                              \
    }

#define BUILD_A(CHI, BUF)                                                         \
    {                                                                             \
        int kb = (CHI) * 16 + hf * 8;                                             \
        unsigned hw[8], lw[8];                                                    \
        _Pragma("unroll")                                                         \
        for (int q = 0; q < 8; ++q) {                                             \
            uchar2 p = lut[kb + q];                                               \
            float f = zrow[p.x] * zrow[p.y];                                      \
            __half h = __float2half_rn(f);                                        \
            float r1 = f - __half2float(h);                                       \
            __half l = __float2half_rn(r1);                                       \
            hw[q] = __half_as_ushort(h);                                          \
            lw[q] = __half_as_ushort(l);                                          \
        }                                                                         \
        unsigned off = (unsigned)((BUF) * SLAB2 + s * ROWB + hf * 16);            \
        *(uint4*)(smem + SM_A + 0 * SLAB + off) =                                 \
            make_uint4(hw[0] | (hw[1] << 16), hw[2] | (hw[3] << 16),              \
                       hw[4] | (hw[5] << 16), hw[6] | (hw[7] << 16));             \
        *(uint4*)(smem + SM_A + 1 * SLAB + off) =                                 \
            make_uint4(lw[0] | (lw[1] << 16), lw[2] | (lw[3] << 16),              \
                       lw[4] | (lw[5] << 16), lw[6] | (lw[7] << 16));             \
    }

    float acc[16][4];
    #pragma unroll
    for (int n = 0; n < 16; ++n)
        #pragma unroll
        for (int q = 0; q < 4; ++q) acc[n][q] = 0.f;

    // ldmatrix source addresses
    uint32_t a_row = (uint32_t)(wid * 16 + (lane & 15));
    uint32_t a_colb = (uint32_t)((lane >> 4) * 16);
    uint32_t b_row = (uint32_t)((lane & 7) + ((lane & 16) ? 8 : 0));
    uint32_t b_colb = (uint32_t)((lane & 8) ? 16 : 0);

    // prologue: chunk 0 into buffer 0
    COPY_B(0, 0)
    BUILD_A(0, 0)
    CP_WAIT0();
    __syncthreads();

    for (int ch = 0; ch < NCH; ++ch) {
        int cur = ch & 1, nxt = cur ^ 1;

        if (ch + 1 < NCH) COPY_B(ch + 1, nxt)

        uint32_t aAddr = sb + SM_A + (uint32_t)(cur * SLAB2) + a_row * ROWB + a_colb;
        uint32_t ah[4], al[4];
        ldm_x4(ah[0], ah[1], ah[2], ah[3], aAddr + 0 * SLAB);
        ldm_x4(al[0], al[1], al[2], al[3], aAddr + 1 * SLAB);

        #pragma unroll
        for (int nt2 = 0; nt2 < 8; ++nt2) {
            uint32_t bAddr = sb + SM_B + (uint32_t)(cur * SLAB2)
                           + (nt2 * 16 + b_row) * ROWB + b_colb;
            uint32_t bh[4], bl[4];
            ldm_x4(bh[0], bh[1], bh[2], bh[3], bAddr + 0 * SLAB);
            ldm_x4(bl[0], bl[1], bl[2], bl[3], bAddr + 1 * SLAB);

            float* d0 = acc[2 * nt2];
            float* d1 = acc[2 * nt2 + 1];
            // 3-product pyramid: hh, lh, hl (omitted ll ~ 2^-22)
            mma16816(d0, ah, bh[0], bh[1]);  mma16816(d1, ah, bh[2], bh[3]);
            mma16816(d0, al, bh[0], bh[1]);  mma16816(d1, al, bh[2], bh[3]);
            mma16816(d0, ah, bl[0], bl[1]);  mma16816(d1, ah, bl[2], bl[3]);
        }

        if (ch + 1 < NCH) BUILD_A(ch + 1, nxt)

        CP_WAIT0();
        __syncthreads();
    }
#undef COPY_B
#undef BUILD_A

    // ---- epilogue: lane holds rows {rA, rA+8}, cols c = nt*8 + 2q + {0,1} ----
    int q = lane & 3, rA = lane >> 2;
    float scA[KN], scB[KN];
    #pragma unroll
    for (int k = 0; k < KN; ++k) { scA[k] = 0.f; scB[k] = 0.f; }
    float gsumA = 0.f, gsumB = 0.f, bestA = -1.f, bestB = -1.f;
    int cbA = 0, cbB = 0;

    #pragma unroll
    for (int nt = 0; nt < 16; ++nt) {
        int c0 = nt * 8 + q * 2;
        float gA0 = __expf(-acc[nt][0]);
        float gA1 = __expf(-acc[nt][1]);
        float gB0 = __expf(-acc[nt][2]);
        float gB1 = __expf(-acc[nt][3]);
        gsumA += gA0 + gA1;  gsumB += gB0 + gB1;
        if (gA0 > bestA) { bestA = gA0; cbA = c0; }
        if (gA1 > bestA) { bestA = gA1; cbA = c0 + 1; }
        if (gB0 > bestB) { bestB = gB0; cbB = c0; }
        if (gB1 > bestB) { bestB = gB1; cbB = c0 + 1; }
        int k0 = scls[c0], k1 = scls[c0 + 1];
        #pragma unroll
        for (int k = 0; k < KN; ++k) {
            if (k0 == k) { scA[k] += gA0; scB[k] += gB0; }
            if (k1 == k) { scA[k] += gA1; scB[k] += gB1; }
        }
    }

    #pragma unroll
    for (int d = 1; d <= 2; d <<= 1) {
        gsumA += __shfl_xor_sync(0xffffffffu, gsumA, d);
        gsumB += __shfl_xor_sync(0xffffffffu, gsumB, d);
        #pragma unroll
        for (int k = 0; k < KN; ++k) {
            scA[k] += __shfl_xor_sync(0xffffffffu, scA[k], d);
            scB[k] += __shfl_xor_sync(0xffffffffu, scB[k], d);
        }
        float obA = __shfl_xor_sync(0xffffffffu, bestA, d);
        int ocA = __shfl_xor_sync(0xffffffffu, cbA, d);
        if (obA > bestA || (obA == bestA && ocA < cbA)) { bestA = obA; cbA = ocA; }
        float obB = __shfl_xor_sync(0xffffffffu, bestB, d);
        int ocB = __shfl_xor_sync(0xffffffffu, cbB, d);
        if (obB > bestB || (obB == bestB && ocB < cbB)) { bestB = obB; cbB = ocB; }
    }

    if (q == 0) {
        long bb = (long)BN * KN;
        {
            long b = (long)blockIdx.x * 128 + wid * 16 + rA;
            float inv = 1.f / (gsumA + EPSV);
            float sb2 = -1.f; int pb = 0;
            float* os = out + b * KN;
            #pragma unroll
            for (int k = 0; k < KN; ++k) {
                float sv = scA[k] * inv;
                os[k] = sv;
                if (sv > sb2) { sb2 = sv; pb = k; }
            }
            if (out_size >= bb + BN)      out[bb + b] = (float)pb;
            if (out_size >= bb + 2 * BN)  out[bb + BN + b] = (float)cbA;
        }
        {
            long b = (long)blockIdx.x * 128 + wid * 16 + rA + 8;
            float inv = 1.f / (gsumB + EPSV);
            float sb2 = -1.f; int pb = 0;
            float* os = out + b * KN;
            #pragma unroll
            for (int k = 0; k < KN; ++k) {
                float sv = scB[k] * inv;
                os[k] = sv;
                if (sv > sb2) { sb2 = sv; pb = k; }
            }
            if (out_size >= bb + BN)      out[bb + b] = (float)pb;
            if (out_size >= bb + 2 * BN)  out[bb + BN + b] = (float)cbB;
        }
    }
}

extern "C" void kernel_launch(void* const* d_in, const int* in_sizes, int n_in,
                              void* d_out, int out_size) {
    const float* data   = (const float*)d_in[0];
    const float* mu     = (const float*)d_in[1];
    const float* S_inv  = (const float*)d_in[2];
    const int*   labels = (const int*)d_in[3];

    cudaFuncSetAttribute(egauss_hmma, cudaFuncAttributeMaxDynamicSharedMemorySize, SMEM_DYN);
    pre_kernel<<<CN, 128>>>(mu, S_inv);
    egauss_hmma<<<BN / 128, 256, SMEM_DYN>>>(data, labels, (float*)d_out, out_size);
}

// round 10
// speedup vs baseline: 6.1402x; 1.0668x over previous
#include <cuda_runtime.h>
#include <cuda_fp16.h>
#include <cstdint>

#define BN 65536
#define CN 128
#define DN 32
#define KN 10
#define EPSV 1e-12f
#define NCH 36            // 576 features / 16 per chunk
#define ROWB 48           // padded row bytes: 16 fp16 (32B) + 16B pad (ldmatrix conflict-free)
#define SLAB 6144         // 128 rows * 48B, one split-chunk image
#define SLAB2 12288       // 2 splits

// Pre-split coefficient images: [split 0..1][chunk 0..35][row=cluster][48B]. 432 KB, L2-resident.
__device__ unsigned char g_Wb[2 * NCH * SLAB];

// ---- dynamic smem layout ----
#define SM_ZS   0                     // 128 samples * 33 floats (stride 33)
#define SM_LUT  16896                 // 576 uchar2
#define SM_SCLS 18048                 // 128 int
#define SM_A    18560                 // 2 buffers x 2*SLAB feature images (also: epilogue partials)
#define SM_B    (SM_A + 2 * SLAB2)    // 2 buffers x 2*SLAB coefficient images
#define SMEM_DYN (SM_B + 2 * SLAB2)   // 67712 B

__device__ __forceinline__ uint32_t smem_u32(const void* p) {
    uint32_t a;
    asm("{ .reg .u64 t; cvta.to.shared.u64 t, %1; cvt.u32.u64 %0, t; }" : "=r"(a) : "l"(p));
    return a;
}
__device__ __forceinline__ void ldm_x4(uint32_t& r0, uint32_t& r1, uint32_t& r2, uint32_t& r3,
                                       uint32_t addr) {
    asm volatile("ldmatrix.sync.aligned.m8n8.x4.shared.b16 {%0,%1,%2,%3}, [%4];"
                 : "=r"(r0), "=r"(r1), "=r"(r2), "=r"(r3) : "r"(addr));
}
__device__ __forceinline__ void mma16816(float* d, const uint32_t* a, uint32_t b0, uint32_t b1) {
    asm volatile("mma.sync.aligned.m16n8k16.row.col.f32.f16.f16.f32 "
                 "{%0,%1,%2,%3}, {%4,%5,%6,%7}, {%8,%9}, {%0,%1,%2,%3};"
                 : "+f"(d[0]), "+f"(d[1]), "+f"(d[2]), "+f"(d[3])
                 : "r"(a[0]), "r"(a[1]), "r"(a[2]), "r"(a[3]), "r"(b0), "r"(b1));
}
__device__ __forceinline__ void cpasync16(uint32_t dst, const void* src) {
    asm volatile("cp.async.cg.shared.global [%0], [%1], 16;" :: "r"(dst), "l"(src));
}
#define CP_COMMIT() asm volatile("cp.async.commit_group;" ::: "memory")
#define CP_WAIT0()  asm volatile("cp.async.wait_group 0;" ::: "memory")

// ---------------------------------------------------------------------------
// Pre-kernel: C_c[i,j] = Mext[i][j] * (i==j ? 0.5 : 1), 2-way fp16 split (h + l).
// ---------------------------------------------------------------------------
__global__ void pre_kernel(const float* __restrict__ mu,
                           const float* __restrict__ S_inv) {
    int c = blockIdx.x, t = threadIdx.x;
    __shared__ float sSm[DN];
    __shared__ float sT3;
    const float* W = S_inv + (size_t)c * DN * DN;
    const float* m = mu + (size_t)c * DN;

    if (t < DN) {
        float a = 0.f;
        #pragma unroll
        for (int e = 0; e < DN; ++e) a = fmaf(W[t * DN + e], m[e], a);
        sSm[t] = a;
    }
    __syncthreads();
    if (t == 0) {
        float a = 0.f;
        #pragma unroll
        for (int d = 0; d < DN; ++d) a = fmaf(m[d], sSm[d], a);
        sT3 = a;
    }
    __syncthreads();

    for (int k = t; k < 576; k += 128) {
        float Cv = 0.f;
        if (k < 561) {
            int i = 0;
            while (i < 32 && k >= 33 * (i + 1) - ((i + 1) * i) / 2) ++i;
            int j = i + (k - (33 * i - (i * (i - 1)) / 2));
            float Mv;
            if (j < 32)        Mv = W[i * DN + j];
            else if (i < 32)   Mv = -sSm[i];
            else               Mv = sT3;
            Cv = (i == j) ? 0.5f * Mv : Mv;
        }
        __half h = __float2half_rn(Cv);
        float r1 = Cv - __half2float(h);
        __half l = __float2half_rn(r1);

        size_t rowoff = (size_t)(k >> 4) * SLAB + (size_t)c * ROWB + (size_t)(k & 15) * 2;
        *(__half*)(g_Wb + 0 * NCH * SLAB + rowoff) = h;
        *(__half*)(g_Wb + 1 * NCH * SLAB + rowoff) = l;
    }
    if (t < 72) {
        int sp = t / 36, ch = t - sp * 36;
        *(uint4*)(g_Wb + (size_t)(sp * NCH + ch) * SLAB + (size_t)c * ROWB + 32) =
            make_uint4(0, 0, 0, 0);
    }
}

// ---------------------------------------------------------------------------
// Main kernel: 512 CTAs x 256 threads; warp tile 32(M)x64(N); fp16 2-split,
// 3-product pyramid; double-buffered cp.async pipeline.
// ---------------------------------------------------------------------------
__global__ __launch_bounds__(256, 2)
void egauss_hmma(const float* __restrict__ data,
                 const int* __restrict__ labels,
                 float* __restrict__ out,
                 int out_size) {
    extern __shared__ char smem[];
    float* zs = (float*)(smem + SM_ZS);
    uchar2* lut = (uchar2*)(smem + SM_LUT);
    int* scls = (int*)(smem + SM_SCLS);
    float* part = (float*)(smem + SM_A);   // epilogue partials: [half][row][13]
    uint32_t sb = smem_u32(smem);

    int tid = threadIdx.x;
    int wid = tid >> 5, lane = tid & 31;
    int wm = wid & 3, wn = wid >> 2;       // warp tile: rows wm*32.., cols wn*64..
    int s = tid >> 1, hf = tid & 1;

    // feature (i,j) LUT; pad features k>=561 -> (0,0)
    for (int k = tid; k < 576; k += 256) {
        int i = 0, j = 0;
        if (k < 561) {
            while (i < 32 && k >= 33 * (i + 1) - ((i + 1) * i) / 2) ++i;
            j = i + (k - (33 * i - (i * (i - 1)) / 2));
        }
        lut[k] = make_uchar2((unsigned char)i, (unsigned char)j);
    }
    if (tid < CN) {
        const int* row = labels + tid * KN;
        int kc = 0;
        #pragma unroll
        for (int k = 0; k < KN; ++k) if (row[k] != 0) kc = k;
        scls[tid] = kc;
    }
    // stage z tile: 128 samples x (32+1) floats, stride 33
    {
        const float4* src = (const float4*)(data + ((size_t)blockIdx.x * 128 + s) * DN + hf * 16);
        #pragma unroll
        for (int q = 0; q < 4; ++q) {
            float4 v = src[q];
            float* dst = zs + s * 33 + hf * 16 + q * 4;
            dst[0] = v.x; dst[1] = v.y; dst[2] = v.z; dst[3] = v.w;
        }
        if (tid < 128) zs[tid * 33 + 32] = 1.f;
    }
    __syncthreads();

    const float* zrow = zs + s * 33;

#define COPY_B(CHI, BUF)                                                          \
    {                                                                             \
        _Pragma("unroll")                                                         \
        for (int sp = 0; sp < 2; ++sp) {                                          \
            const unsigned char* gsrc = g_Wb + (size_t)(sp * NCH + (CHI)) * SLAB; \
            uint32_t dbase = sb + SM_B + (BUF) * SLAB2 + sp * SLAB;               \
            _Pragma("unroll")                                                     \
            for (int r = 0; r < 2; ++r) {                                         \
                int idx = tid + 256 * r;                                          \
                if (idx < SLAB / 16)                                              \
                    cpasync16(dbase + (uint32_t)(idx * 16), gsrc + idx * 16);     \
            }                                                                     \
        }                                                                         \
        CP_COMMIT();                                                              \
    }

#define BUILD_A(CHI, BUF)                                                         \
    {                                                                             \
        int kb = (CHI) * 16 + hf * 8;                                             \
        unsigned hw[4], lw[4];                                                    \
        _Pragma("unroll")                                                         \
        for (int q = 0; q < 4; ++q) {                                             \
            uchar2 p0 = lut[kb + 2 * q], p1 = lut[kb + 2 * q + 1];                \
            float f0 = zrow[p0.x] * zrow[p0.y];                                   \
            float f1 = zrow[p1.x] * zrow[p1.y];                                   \
            __half2 h2 = __floats2half2_rn(f0, f1);                               \
            float r0 = f0 - __low2float(h2);                                      \
            float r1 = f1 - __high2float(h2);                                     \
            __half2 l2 = __floats2half2_rn(r0, r1);                               \
            hw[q] = *reinterpret_cast<unsigned*>(&h2);                            \
            lw[q] = *reinterpret_cast<unsigned*>(&l2);                            \
        }                                                                         \
        unsigned off = (unsigned)((BUF) * SLAB2 + s * ROWB + hf * 16);            \
        *(uint4*)(smem + SM_A + 0 * SLAB + off) = make_uint4(hw[0], hw[1], hw[2], hw[3]); \
        *(uint4*)(smem + SM_A + 1 * SLAB + off) = make_uint4(lw[0], lw[1], lw[2], lw[3]); \
    }

    float acc[2][8][4];
    #pragma unroll
    for (int mt = 0; mt < 2; ++mt)
        #pragma unroll
        for (int g = 0; g < 8; ++g)
            #pragma unroll
            for (int q = 0; q < 4; ++q) acc[mt][g][q] = 0.f;

    // ldmatrix addressing
    uint32_t a_row = (uint32_t)(wm * 32 + (lane & 15));
    uint32_t a_colb = (uint32_t)((lane >> 4) * 16);
    uint32_t b_row = (uint32_t)(wn * 64 + (lane & 7) + ((lane & 16) ? 8 : 0));
    uint32_t b_colb = (uint32_t)((lane & 8) ? 16 : 0);

    COPY_B(0, 0)
    BUILD_A(0, 0)
    CP_WAIT0();
    __syncthreads();

    for (int ch = 0; ch < NCH; ++ch) {
        int cur = ch & 1, nxt = cur ^ 1;

        if (ch + 1 < NCH) COPY_B(ch + 1, nxt)

        uint32_t aAddr = sb + SM_A + (uint32_t)(cur * SLAB2) + a_row * ROWB + a_colb;
        uint32_t ah[2][4], al[2][4];
        #pragma unroll
        for (int mt = 0; mt < 2; ++mt) {
            ldm_x4(ah[mt][0], ah[mt][1], ah[mt][2], ah[mt][3],
                   aAddr + (uint32_t)(mt * 16 * ROWB) + 0 * SLAB);
            ldm_x4(al[mt][0], al[mt][1], al[mt][2], al[mt][3],
                   aAddr + (uint32_t)(mt * 16 * ROWB) + 1 * SLAB);
        }

        #pragma unroll
        for (int nt2 = 0; nt2 < 4; ++nt2) {
            uint32_t bAddr = sb + SM_B + (uint32_t)(cur * SLAB2)
                           + (uint32_t)(nt2 * 16) * ROWB + b_row * ROWB + b_colb;
            uint32_t bh[4], bl[4];
            ldm_x4(bh[0], bh[1], bh[2], bh[3], bAddr + 0 * SLAB);
            ldm_x4(bl[0], bl[1], bl[2], bl[3], bAddr + 1 * SLAB);

            #pragma unroll
            for (int mt = 0; mt < 2; ++mt) {
                float* d0 = acc[mt][2 * nt2];
                float* d1 = acc[mt][2 * nt2 + 1];
                mma16816(d0, ah[mt], bh[0], bh[1]);  mma16816(d1, ah[mt], bh[2], bh[3]);
                mma16816(d0, al[mt], bh[0], bh[1]);  mma16816(d1, al[mt], bh[2], bh[3]);
                mma16816(d0, ah[mt], bl[0], bl[1]);  mma16816(d1, ah[mt], bl[2], bl[3]);
            }
        }

        if (ch + 1 < NCH) BUILD_A(ch + 1, nxt)

        CP_WAIT0();
        __syncthreads();
    }
#undef COPY_B
#undef BUILD_A

    // ---- epilogue pass 1: per-warp partials over its 64-column half ----
    // lane holds rows wm*32 + mt*16 + {rA, rA+8}; cols wn*64 + g*8 + q*2 + {0,1}
    int q = lane & 3, rA = lane >> 2;

    #pragma unroll
    for (int mt = 0; mt < 2; ++mt) {
        float scA[KN], scB[KN];
        #pragma unroll
        for (int k = 0; k < KN; ++k) { scA[k] = 0.f; scB[k] = 0.f; }
        float gsumA = 0.f, gsumB = 0.f, bestA = -1.f, bestB = -1.f;
        int cbA = 0, cbB = 0;

        #pragma unroll
        for (int g = 0; g < 8; ++g) {
            int c0 = wn * 64 + g * 8 + q * 2;
            float gA0 = __expf(-acc[mt][g][0]);
            float gA1 = __expf(-acc[mt][g][1]);
            float gB0 = __expf(-acc[mt][g][2]);
            float gB1 = __expf(-acc[mt][g][3]);
            gsumA += gA0 + gA1;  gsumB += gB0 + gB1;
            if (gA0 > bestA) { bestA = gA0; cbA = c0; }
            if (gA1 > bestA) { bestA = gA1; cbA = c0 + 1; }
            if (gB0 > bestB) { bestB = gB0; cbB = c0; }
            if (gB1 > bestB) { bestB = gB1; cbB = c0 + 1; }
            int k0 = scls[c0], k1 = scls[c0 + 1];
            #pragma unroll
            for (int k = 0; k < KN; ++k) {
                if (k0 == k) { scA[k] += gA0; scB[k] += gB0; }
                if (k1 == k) { scA[k] += gA1; scB[k] += gB1; }
            }
        }

        #pragma unroll
        for (int d = 1; d <= 2; d <<= 1) {
            gsumA += __shfl_xor_sync(0xffffffffu, gsumA, d);
            gsumB += __shfl_xor_sync(0xffffffffu, gsumB, d);
            #pragma unroll
            for (int k = 0; k < KN; ++k) {
                scA[k] += __shfl_xor_sync(0xffffffffu, scA[k], d);
                scB[k] += __shfl_xor_sync(0xffffffffu, scB[k], d);
            }
            float obA = __shfl_xor_sync(0xffffffffu, bestA, d);
            int ocA = __shfl_xor_sync(0xffffffffu, cbA, d);
            if (obA > bestA || (obA == bestA && ocA < cbA)) { bestA = obA; cbA = ocA; }
            float obB = __shfl_xor_sync(0xffffffffu, bestB, d);
            int ocB = __shfl_xor_sync(0xffffffffu, cbB, d);
            if (obB > bestB || (obB == bestB && ocB < cbB)) { bestB = obB; cbB = ocB; }
        }

        if (q == 0) {
            int r0 = wm * 32 + mt * 16 + rA;
            float* pA = part + (size_t)(wn * 128 + r0) * 13;
            #pragma unroll
            for (int k = 0; k < KN; ++k) pA[k] = scA[k];
            pA[10] = gsumA; pA[11] = bestA; pA[12] = (float)cbA;
            float* pB = part + (size_t)(wn * 128 + r0 + 8) * 13;
            #pragma unroll
            for (int k = 0; k < KN; ++k) pB[k] = scB[k];
            pB[10] = gsumB; pB[11] = bestB; pB[12] = (float)cbB;
        }
    }
    __syncthreads();

    // ---- epilogue pass 2: combine halves, normalize, argmax, write ----
    if (tid < 128) {
        const float* p0 = part + (size_t)tid * 13;
        const float* p1 = part + (size_t)(128 + tid) * 13;
        float gsum = p0[10] + p1[10];
        float inv = 1.f / (gsum + EPSV);

        long b = (long)blockIdx.x * 128 + tid;
        float* os = out + b * KN;
        float sbv = -1.f; int pb = 0;
        #pragma unroll
        for (int k = 0; k < KN; ++k) {
            float sv = (p0[k] + p1[k]) * inv;
            os[k] = sv;
            if (sv > sbv) { sbv = sv; pb = k; }
        }
        float cb = (p1[11] > p0[11]) ? p1[12] : p0[12];   // half0 wins ties (lower index)
        long bb = (long)BN * KN;
        if (out_size >= bb + BN)      out[bb + b] = (float)pb;
        if (out_size >= bb + 2 * BN)  out[bb + BN + b] = cb;
    }
}

extern "C" void kernel_launch(void* const* d_in, const int* in_sizes, int n_in,
                              void* d_out, int out_size) {
    const float* data   = (const float*)d_in[0];
    const float* mu     = (const float*)d_in[1];
    const float* S_inv  = (const float*)d_in[2];
    const int*   labels = (const int*)d_in[3];

    cudaFuncSetAttribute(egauss_hmma, cudaFuncAttributeMaxDynamicSharedMemorySize, SMEM_DYN);
    pre_kernel<<<CN, 128>>>(mu, S_inv);
    egauss_hmma<<<BN / 128, 256, SMEM_DYN>>>(data, labels, (float*)d_out, out_size);
}

// round 11
// speedup vs baseline: 6.2396x; 1.0162x over previous
#include <cuda_runtime.h>
#include <cuda_fp16.h>
#include <cstdint>

#define BN 65536
#define CN 128
#define DN 32
#define KN 10
#define EPSV 1e-12f
#define NCH 18            // 576 features / 32 per stage
#define ROWB 80           // 32 fp16 (64B) + 16B pad; 80/16=5 coprime 8 -> ldmatrix conflict-free
#define SLAB 10240        // 128 rows * 80B, one split-stage image
#define SLAB2 20480       // 2 splits

// Pre-split coefficient images: [split 0..1][stage 0..17][row=cluster][80B]. 360 KB, L2-resident.
__device__ unsigned char g_Wb[2 * NCH * SLAB];

// ---- dynamic smem layout ----
#define SM_ZS   0                     // 128 samples * 33 floats (stride 33)
#define SM_SCLS 16896                 // 128 int
#define SM_LUT4 17408                 // 288 uchar4 (feature pairs)
#define SM_A    18560                 // 2 buffers x 2*SLAB feature images (also epilogue partials)
#define SM_B    (SM_A + 2 * SLAB2)    // 2 buffers x 2*SLAB coefficient images
#define SMEM_DYN (SM_B + 2 * SLAB2)   // 100480 B -> 2 CTAs/SM

__device__ __forceinline__ uint32_t smem_u32(const void* p) {
    uint32_t a;
    asm("{ .reg .u64 t; cvta.to.shared.u64 t, %1; cvt.u32.u64 %0, t; }" : "=r"(a) : "l"(p));
    return a;
}
__device__ __forceinline__ void ldm_x4(uint32_t& r0, uint32_t& r1, uint32_t& r2, uint32_t& r3,
                                       uint32_t addr) {
    asm volatile("ldmatrix.sync.aligned.m8n8.x4.shared.b16 {%0,%1,%2,%3}, [%4];"
                 : "=r"(r0), "=r"(r1), "=r"(r2), "=r"(r3) : "r"(addr));
}
__device__ __forceinline__ void mma16816(float* d, const uint32_t* a, uint32_t b0, uint32_t b1) {
    asm volatile("mma.sync.aligned.m16n8k16.row.col.f32.f16.f16.f32 "
                 "{%0,%1,%2,%3}, {%4,%5,%6,%7}, {%8,%9}, {%0,%1,%2,%3};"
                 : "+f"(d[0]), "+f"(d[1]), "+f"(d[2]), "+f"(d[3])
                 : "r"(a[0]), "r"(a[1]), "r"(a[2]), "r"(a[3]), "r"(b0), "r"(b1));
}
__device__ __forceinline__ void cpasync16(uint32_t dst, const void* src) {
    asm volatile("cp.async.cg.shared.global [%0], [%1], 16;" :: "r"(dst), "l"(src));
}
#define CP_COMMIT() asm volatile("cp.async.commit_group;" ::: "memory")
#define CP_WAIT0()  asm volatile("cp.async.wait_group 0;" ::: "memory")

// ---------------------------------------------------------------------------
// Pre-kernel: C_c[i,j] = Mext[i][j] * (i==j ? 0.5 : 1), 2-way fp16 split (h + l).
// ---------------------------------------------------------------------------
__global__ void pre_kernel(const float* __restrict__ mu,
                           const float* __restrict__ S_inv) {
    int c = blockIdx.x, t = threadIdx.x;
    __shared__ float sSm[DN];
    __shared__ float sT3;
    const float* W = S_inv + (size_t)c * DN * DN;
    const float* m = mu + (size_t)c * DN;

    if (t < DN) {
        float a = 0.f;
        #pragma unroll
        for (int e = 0; e < DN; ++e) a = fmaf(W[t * DN + e], m[e], a);
        sSm[t] = a;
    }
    __syncthreads();
    if (t == 0) {
        float a = 0.f;
        #pragma unroll
        for (int d = 0; d < DN; ++d) a = fmaf(m[d], sSm[d], a);
        sT3 = a;
    }
    __syncthreads();

    for (int k = t; k < 576; k += 128) {
        float Cv = 0.f;
        if (k < 561) {
            int i = 0;
            while (i < 32 && k >= 33 * (i + 1) - ((i + 1) * i) / 2) ++i;
            int j = i + (k - (33 * i - (i * (i - 1)) / 2));
            float Mv;
            if (j < 32)        Mv = W[i * DN + j];
            else if (i < 32)   Mv = -sSm[i];
            else               Mv = sT3;
            Cv = (i == j) ? 0.5f * Mv : Mv;
        }
        __half h = __float2half_rn(Cv);
        float r1 = Cv - __half2float(h);
        __half l = __float2half_rn(r1);

        size_t rowoff = (size_t)(k >> 5) * SLAB + (size_t)c * ROWB + (size_t)(k & 31) * 2;
        *(__half*)(g_Wb + 0 * NCH * SLAB + rowoff) = h;
        *(__half*)(g_Wb + 1 * NCH * SLAB + rowoff) = l;
    }
    // zero the 16B pad of this cluster's row in all 36 images
    if (t < 36) {
        int sp = t / NCH, ch = t - sp * NCH;
        *(uint4*)(g_Wb + (size_t)(sp * NCH + ch) * SLAB + (size_t)c * ROWB + 64) =
            make_uint4(0, 0, 0, 0);
    }
}

// ---------------------------------------------------------------------------
// Main kernel: 512 CTAs x 256 threads; warp tile 32(M)x64(N); K=32 per stage,
// 18 stages; fp16 2-split, 3-product pyramid; double-buffered cp.async.
// ---------------------------------------------------------------------------
__global__ __launch_bounds__(256, 2)
void egauss_hmma(const float* __restrict__ data,
                 const int* __restrict__ labels,
                 float* __restrict__ out,
                 int out_size) {
    extern __shared__ char smem[];
    float* zs = (float*)(smem + SM_ZS);
    int* scls = (int*)(smem + SM_SCLS);
    uchar4* lut4 = (uchar4*)(smem + SM_LUT4);
    float* part = (float*)(smem + SM_A);   // epilogue partials: [half][row][13]
    uint32_t sb = smem_u32(smem);

    int tid = threadIdx.x;
    int wid = tid >> 5, lane = tid & 31;
    int wm = wid & 3, wn = wid >> 2;       // warp tile: rows wm*32.., cols wn*64..
    int s = tid >> 1, hf = tid & 1;

    // feature-pair LUT: entry p -> (i,j) of features 2p and 2p+1 (pad -> (0,0))
    for (int p = tid; p < 288; p += 256) {
        int idx[2][2];
        #pragma unroll
        for (int h = 0; h < 2; ++h) {
            int k = 2 * p + h, i = 0, j = 0;
            if (k < 561) {
                while (i < 32 && k >= 33 * (i + 1) - ((i + 1) * i) / 2) ++i;
                j = i + (k - (33 * i - (i * (i - 1)) / 2));
            }
            idx[h][0] = i; idx[h][1] = j;
        }
        lut4[p] = make_uchar4((unsigned char)idx[0][0], (unsigned char)idx[0][1],
                              (unsigned char)idx[1][0], (unsigned char)idx[1][1]);
    }
    if (tid < CN) {
        const int* row = labels + tid * KN;
        int kc = 0;
        #pragma unroll
        for (int k = 0; k < KN; ++k) if (row[k] != 0) kc = k;
        scls[tid] = kc;
    }
    // stage z tile: 128 samples x (32+1) floats, stride 33
    {
        const float4* src = (const float4*)(data + ((size_t)blockIdx.x * 128 + s) * DN + hf * 16);
        #pragma unroll
        for (int q = 0; q < 4; ++q) {
            float4 v = src[q];
            float* dst = zs + s * 33 + hf * 16 + q * 4;
            dst[0] = v.x; dst[1] = v.y; dst[2] = v.z; dst[3] = v.w;
        }
        if (tid < 128) zs[tid * 33 + 32] = 1.f;
    }
    __syncthreads();

    const float* zrow = zs + s * 33;

#define COPY_B(CHI, BUF)                                                          \
    {                                                                             \
        _Pragma("unroll")                                                         \
        for (int sp = 0; sp < 2; ++sp) {                                          \
            const unsigned char* gsrc = g_Wb + (size_t)(sp * NCH + (CHI)) * SLAB; \
            uint32_t dbase = sb + SM_B + (BUF) * SLAB2 + sp * SLAB;               \
            _Pragma("unroll")                                                     \
            for (int r = 0; r < 3; ++r) {                                         \
                int idx = tid + 256 * r;                                          \
                if (idx < SLAB / 16)                                              \
                    cpasync16(dbase + (uint32_t)(idx * 16), gsrc + idx * 16);     \
            }                                                                     \
        }                                                                         \
        CP_COMMIT();                                                              \
    }

    // thread (s, hf) builds 16 features (8 pairs) of row s: k = CHI*32 + hf*16 ..
#define BUILD_A(CHI, BUF)                                                         \
    {                                                                             \
        int pb = (CHI) * 16 + hf * 8;                                             \
        unsigned hw[8], lw[8];                                                    \
        _Pragma("unroll")                                                         \
        for (int p = 0; p < 8; ++p) {                                             \
            uchar4 e = lut4[pb + p];                                              \
            float f0 = zrow[e.x] * zrow[e.y];                                     \
            float f1 = zrow[e.z] * zrow[e.w];                                     \
            __half2 h2 = __floats2half2_rn(f0, f1);                               \
            float r0 = f0 - __low2float(h2);                                      \
            float r1 = f1 - __high2float(h2);                                     \
            __half2 l2 = __floats2half2_rn(r0, r1);                               \
            hw[p] = *reinterpret_cast<unsigned*>(&h2);                            \
            lw[p] = *reinterpret_cast<unsigned*>(&l2);                            \
        }                                                                         \
        unsigned off = (unsigned)((BUF) * SLAB2 + s * ROWB + hf * 32);            \
        *(uint4*)(smem + SM_A + 0 * SLAB + off)      = make_uint4(hw[0], hw[1], hw[2], hw[3]); \
        *(uint4*)(smem + SM_A + 0 * SLAB + off + 16) = make_uint4(hw[4], hw[5], hw[6], hw[7]); \
        *(uint4*)(smem + SM_A + 1 * SLAB + off)      = make_uint4(lw[0], lw[1], lw[2], lw[3]); \
        *(uint4*)(smem + SM_A + 1 * SLAB + off + 16) = make_uint4(lw[4], lw[5], lw[6], lw[7]); \
    }

    float acc[2][8][4];
    #pragma unroll
    for (int mt = 0; mt < 2; ++mt)
        #pragma unroll
        for (int g = 0; g < 8; ++g)
            #pragma unroll
            for (int q = 0; q < 4; ++q) acc[mt][g][q] = 0.f;

    // ldmatrix addressing
    uint32_t a_row = (uint32_t)(wm * 32 + (lane & 15));
    uint32_t a_colb = (uint32_t)((lane >> 4) * 16);
    uint32_t b_row = (uint32_t)(wn * 64 + (lane & 7) + ((lane & 16) ? 8 : 0));
    uint32_t b_colb = (uint32_t)((lane & 8) ? 16 : 0);

    COPY_B(0, 0)
    BUILD_A(0, 0)
    CP_WAIT0();
    __syncthreads();

    for (int ch = 0; ch < NCH; ++ch) {
        int cur = ch & 1, nxt = cur ^ 1;

        if (ch + 1 < NCH) COPY_B(ch + 1, nxt)

        #pragma unroll
        for (int ks = 0; ks < 2; ++ks) {
            uint32_t aAddr = sb + SM_A + (uint32_t)(cur * SLAB2)
                           + a_row * ROWB + a_colb + (uint32_t)(ks * 32);
            uint32_t ah[2][4], al[2][4];
            #pragma unroll
            for (int mt = 0; mt < 2; ++mt) {
                ldm_x4(ah[mt][0], ah[mt][1], ah[mt][2], ah[mt][3],
                       aAddr + (uint32_t)(mt * 16 * ROWB) + 0 * SLAB);
                ldm_x4(al[mt][0], al[mt][1], al[mt][2], al[mt][3],
                       aAddr + (uint32_t)(mt * 16 * ROWB) + 1 * SLAB);
            }

            #pragma unroll
            for (int nt2 = 0; nt2 < 4; ++nt2) {
                uint32_t bAddr = sb + SM_B + (uint32_t)(cur * SLAB2)
                               + (uint32_t)(nt2 * 16) * ROWB + b_row * ROWB + b_colb
                               + (uint32_t)(ks * 32);
                uint32_t bh[4], bl[4];
                ldm_x4(bh[0], bh[1], bh[2], bh[3], bAddr + 0 * SLAB);
                ldm_x4(bl[0], bl[1], bl[2], bl[3], bAddr + 1 * SLAB);

                #pragma unroll
                for (int mt = 0; mt < 2; ++mt) {
                    float* d0 = acc[mt][2 * nt2];
                    float* d1 = acc[mt][2 * nt2 + 1];
                    mma16816(d0, ah[mt], bh[0], bh[1]);  mma16816(d1, ah[mt], bh[2], bh[3]);
                    mma16816(d0, al[mt], bh[0], bh[1]);  mma16816(d1, al[mt], bh[2], bh[3]);
                    mma16816(d0, ah[mt], bl[0], bl[1]);  mma16816(d1, ah[mt], bl[2], bl[3]);
                }
            }
        }

        if (ch + 1 < NCH) BUILD_A(ch + 1, nxt)

        CP_WAIT0();
        __syncthreads();
    }
#undef COPY_B
#undef BUILD_A

    // ---- epilogue pass 1: per-warp partials over its 64-column half ----
    int q = lane & 3, rA = lane >> 2;

    #pragma unroll
    for (int mt = 0; mt < 2; ++mt) {
        float scA[KN], scB[KN];
        #pragma unroll
        for (int k = 0; k < KN; ++k) { scA[k] = 0.f; scB[k] = 0.f; }
        float gsumA = 0.f, gsumB = 0.f, bestA = -1.f, bestB = -1.f;
        int cbA = 0, cbB = 0;

        #pragma unroll
        for (int g = 0; g < 8; ++g) {
            int c0 = wn * 64 + g * 8 + q * 2;
            float gA0 = __expf(-acc[mt][g][0]);
            float gA1 = __expf(-acc[mt][g][1]);
            float gB0 = __expf(-acc[mt][g][2]);
            float gB1 = __expf(-acc[mt][g][3]);
            gsumA += gA0 + gA1;  gsumB += gB0 + gB1;
            if (gA0 > bestA) { bestA = gA0; cbA = c0; }
            if (gA1 > bestA) { bestA = gA1; cbA = c0 + 1; }
            if (gB0 > bestB) { bestB = gB0; cbB = c0; }
            if (gB1 > bestB) { bestB = gB1; cbB = c0 + 1; }
            int k0 = scls[c0], k1 = scls[c0 + 1];
            #pragma unroll
            for (int k = 0; k < KN; ++k) {
                if (k0 == k) { scA[k] += gA0; scB[k] += gB0; }
                if (k1 == k) { scA[k] += gA1; scB[k] += gB1; }
            }
        }

        #pragma unroll
        for (int d = 1; d <= 2; d <<= 1) {
            gsumA += __shfl_xor_sync(0xffffffffu, gsumA, d);
            gsumB += __shfl_xor_sync(0xffffffffu, gsumB, d);
            #pragma unroll
            for (int k = 0; k < KN; ++k) {
                scA[k] += __shfl_xor_sync(0xffffffffu, scA[k], d);
                scB[k] += __shfl_xor_sync(0xffffffffu, scB[k], d);
            }
            float obA = __shfl_xor_sync(0xffffffffu, bestA, d);
            int ocA = __shfl_xor_sync(0xffffffffu, cbA, d);
            if (obA > bestA || (obA == bestA && ocA < cbA)) { bestA = obA; cbA = ocA; }
            float obB = __shfl_xor_sync(0xffffffffu, bestB, d);
            int ocB = __shfl_xor_sync(0xffffffffu, cbB, d);
            if (obB > bestB || (obB == bestB && ocB < cbB)) { bestB = obB; cbB = ocB; }
        }

        if (q == 0) {
            int r0 = wm * 32 + mt * 16 + rA;
            float* pA = part + (size_t)(wn * 128 + r0) * 13;
            #pragma unroll
            for (int k = 0; k < KN; ++k) pA[k] = scA[k];
            pA[10] = gsumA; pA[11] = bestA; pA[12] = (float)cbA;
            float* pB = part + (size_t)(wn * 128 + r0 + 8) * 13;
            #pragma unroll
            for (int k = 0; k < KN; ++k) pB[k] = scB[k];
            pB[10] = gsumB; pB[11] = bestB; pB[12] = (float)cbB;
        }
    }
    __syncthreads();

    // ---- epilogue pass 2: combine halves, normalize, argmax, write ----
    if (tid < 128) {
        const float* p0 = part + (size_t)tid * 13;
        const float* p1 = part + (size_t)(128 + tid) * 13;
        float gsum = p0[10] + p1[10];
        float inv = 1.f / (gsum + EPSV);

        long b = (long)blockIdx.x * 128 + tid;
        float* os = out + b * KN;
        float sbv = -1.f; int pb = 0;
        #pragma unroll
        for (int k = 0; k < KN; ++k) {
            float sv = (p0[k] + p1[k]) * inv;
            os[k] = sv;
            if (sv > sbv) { sbv = sv; pb = k; }
        }
        float cb = (p1[11] > p0[11]) ? p1[12] : p0[12];   // half0 wins ties (lower index)
        long bb = (long)BN * KN;
        if (out_size >= bb + BN)      out[bb + b] = (float)pb;
        if (out_size >= bb + 2 * BN)  out[bb + BN + b] = cb;
    }
}

extern "C" void kernel_launch(void* const* d_in, const int* in_sizes, int n_in,
                              void* d_out, int out_size) {
    const float* data   = (const float*)d_in[0];
    const float* mu     = (const float*)d_in[1];
    const float* S_inv  = (const float*)d_in[2];
    const int*   labels = (const int*)d_in[3];

    cudaFuncSetAttribute(egauss_hmma, cudaFuncAttributeMaxDynamicSharedMemorySize, SMEM_DYN);
    pre_kernel<<<CN, 128>>>(mu, S_inv);
    egauss_hmma<<<BN / 128, 256, SMEM_DYN>>>(data, labels, (float*)d_out, out_size);
}